// round 13
// baseline (speedup 1.0000x reference)
#include <cuda_runtime.h>
#include <math.h>
#include <stdint.h>

#define BB 32
#define PP 1024
#define KNN 20
#define NPTS (BB*PP)

// ---------------- scratch (device globals; no allocs allowed) ----------------
__device__ __align__(16) float g_x1[NPTS*64];
__device__ __align__(16) float g_x2[NPTS*128];
__device__ int g_idx[NPTS*KNN];
__device__ unsigned int g_pool[BB*1024];
__device__ __align__(16) float g_h0[BB*512];
__device__ __align__(16) float g_w01[8*64];
__device__ __align__(16) float g_b01[64];

// ---------------- tf32 mma helpers ----------------
__device__ __forceinline__ uint32_t f2tf(float x) {
    uint32_t r; asm("cvt.rna.tf32.f32 %0, %1;" : "=r"(r) : "f"(x)); return r;
}
__device__ __forceinline__ float tfbits(float x) {
    return __uint_as_float(f2tf(x));
}
__device__ __forceinline__ void mma8(float& c0, float& c1, float& c2, float& c3,
                                     uint32_t a0, uint32_t a1, uint32_t a2, uint32_t a3,
                                     uint32_t b0, uint32_t b1)
{
    asm volatile("mma.sync.aligned.m16n8k8.row.col.f32.tf32.tf32.f32 "
                 "{%0,%1,%2,%3},{%4,%5,%6,%7},{%8,%9},{%0,%1,%2,%3};"
                 : "+f"(c0), "+f"(c1), "+f"(c2), "+f"(c3)
                 : "r"(a0), "r"(a1), "r"(a2), "r"(a3), "r"(b0), "r"(b1));
}

// top-k insertion (strict <, keeps earliest index on ties — matches jax top_k).
// Early break: once the new element stops bubbling, the sorted prefix guarantees
// no further swaps — final list is IDENTICAL to the full pass.
__device__ __forceinline__ void topk_insert(float* bd, int* bi, float d, int j)
{
    if (d < bd[KNN-1]) {
        bd[KNN-1] = d; bi[KNN-1] = j;
#pragma unroll
        for (int t = KNN-1; t > 0; t--) {
            if (!(bd[t] < bd[t-1])) break;
            float td = bd[t]; bd[t] = bd[t-1]; bd[t-1] = td;
            int ti = bi[t]; bi[t] = bi[t-1]; bi[t-1] = ti;
        }
    }
}

// 5 m-tiles x 2 n-tiles warp GEMM (used by conv1)
__device__ __forceinline__ void mma_5x2(
    const float* sD, const float* sW, float acc[5][2][4],
    int mB, int nB, int g4, int tig, int ksteps, int ldd, int ldw)
{
#pragma unroll
    for (int mi = 0; mi < 5; mi++)
#pragma unroll
        for (int ni = 0; ni < 2; ni++)
#pragma unroll
            for (int c = 0; c < 4; c++) acc[mi][ni][c] = 0.f;
#pragma unroll 1
    for (int ks = 0; ks < ksteps; ks++) {
        int k0 = ks * 8;
        uint32_t A[5][4];
#pragma unroll
        for (int mi = 0; mi < 5; mi++) {
            int row = mB + mi*16 + g4;
            A[mi][0] = __float_as_uint(sD[row*ldd + k0 + tig]);
            A[mi][1] = __float_as_uint(sD[(row+8)*ldd + k0 + tig]);
            A[mi][2] = __float_as_uint(sD[row*ldd + k0 + tig + 4]);
            A[mi][3] = __float_as_uint(sD[(row+8)*ldd + k0 + tig + 4]);
        }
        uint32_t Bf[2][2];
#pragma unroll
        for (int ni = 0; ni < 2; ni++) {
            int col = nB + ni*8 + g4;
            Bf[ni][0] = __float_as_uint(sW[(k0+tig)*ldw + col]);
            Bf[ni][1] = __float_as_uint(sW[(k0+tig+4)*ldw + col]);
        }
#pragma unroll
        for (int mi = 0; mi < 5; mi++)
#pragma unroll
            for (int ni = 0; ni < 2; ni++)
                mma8(acc[mi][ni][0], acc[mi][ni][1], acc[mi][ni][2], acc[mi][ni][3],
                     A[mi][0], A[mi][1], A[mi][2], A[mi][3], Bf[ni][0], Bf[ni][1]);
    }
}

__device__ __forceinline__ void wb_5x2(
    float* sD, float acc[5][2][4], const float* bias,
    int mB, int nB, int g4, int tig, int ldd, int mode)
{
#pragma unroll
    for (int mi = 0; mi < 5; mi++) {
#pragma unroll
        for (int ni = 0; ni < 2; ni++) {
            int row = mB + mi*16 + g4, col = nB + ni*8 + tig*2;
            float v0 = acc[mi][ni][0], v1 = acc[mi][ni][1];
            float v2 = acc[mi][ni][2], v3 = acc[mi][ni][3];
            float ba = bias[col], bb = bias[col+1];
            v0 += ba; v1 += bb; v2 += ba; v3 += bb;
            if (mode == 1) {
                v0 = fmaxf(v0, 0.f); v1 = fmaxf(v1, 0.f);
                v2 = fmaxf(v2, 0.f); v3 = fmaxf(v3, 0.f);
            }
            v0 = tfbits(v0); v1 = tfbits(v1); v2 = tfbits(v2); v3 = tfbits(v3);
            sD[row*ldd + col] = v0;     sD[row*ldd + col + 1] = v1;
            sD[(row+8)*ldd + col] = v2; sD[(row+8)*ldd + col + 1] = v3;
        }
    }
}

// ---------------- prologue: W01 = W0 @ W1, b01 = b0 @ W1 + b1 (exact fp32) ----------------
__global__ __launch_bounds__(512) void fuse_w01_kernel(
    const float* __restrict__ w0, const float* __restrict__ b0,
    const float* __restrict__ w1, const float* __restrict__ b1)
{
    int tid = threadIdx.x;
    if (tid < 384) {
        int c = tid >> 6, o = tid & 63;
        float s = 0.f;
        for (int h = 0; h < 64; h++) s = fmaf(w0[c*64 + h], w1[h*64 + o], s);
        g_w01[c*64 + o] = s;
    } else if (tid < 448) {
        int o = tid - 384;
        float s = b1[o];
        for (int h = 0; h < 64; h++) s = fmaf(b0[h], w1[h*64 + o], s);
        g_b01[o] = s;
    }
}

// ---------------- KNN over 3-D positions: split-scan (2 threads/point) + pool zero ----------------
__global__ __launch_bounds__(512) void knn_pos_kernel(const float* __restrict__ pos)
{
    extern __shared__ float smk[];
    float4* spos = (float4*)smk;                     // 1024 float4
    float*  sbd  = smk + 4096;                       // 256*20
    int*    sbi  = (int*)(smk + 4096 + 5120);        // 256*20
    int tid = threadIdx.x;
    int lb = blockIdx.y*4 + blockIdx.x;
    if (tid < 256) g_pool[lb*256 + tid] = 0u;
    int b = blockIdx.y;
    const float* p = pos + (size_t)b * PP * 3;
    for (int j = tid; j < PP; j += 512) {
        float x = p[3*j], y = p[3*j+1], z = p[3*j+2];
        spos[j] = make_float4(x, y, z, x*x + y*y + z*z);
    }
    __syncthreads();
    int pt = tid & 255, s = tid >> 8;
    int il = blockIdx.x * 256 + pt;
    float4 me = spos[il];
    float xi = me.x, yi = me.y, zi = me.z, sqi = me.w;
    float bd[KNN]; int bi[KNN];
#pragma unroll
    for (int t = 0; t < KNN; t++) { bd[t] = 3.4e38f; bi[t] = 0; }
    int j4base = s * 128;
    for (int j4 = j4base; j4 < j4base + 128; j4++) {
        float4 v0 = spos[4*j4+0], v1 = spos[4*j4+1], v2 = spos[4*j4+2], v3 = spos[4*j4+3];
        float d0 = sqi + v0.w - 2.0f*(xi*v0.x + yi*v0.y + zi*v0.z);
        float d1 = sqi + v1.w - 2.0f*(xi*v1.x + yi*v1.y + zi*v1.z);
        float d2 = sqi + v2.w - 2.0f*(xi*v2.x + yi*v2.y + zi*v2.z);
        float d3 = sqi + v3.w - 2.0f*(xi*v3.x + yi*v3.y + zi*v3.z);
        float mn = fminf(fminf(d0, d1), fminf(d2, d3));
        if (mn < bd[KNN-1]) {
            topk_insert(bd, bi, d0, 4*j4+0);
            topk_insert(bd, bi, d1, 4*j4+1);
            topk_insert(bd, bi, d2, 4*j4+2);
            topk_insert(bd, bi, d3, 4*j4+3);
        }
    }
    if (s == 1) {
#pragma unroll
        for (int t = 0; t < KNN; t++) { sbd[pt*KNN + t] = bd[t]; sbi[pt*KNN + t] = bi[t]; }
    }
    __syncthreads();
    if (s == 0) {
        for (int t = 0; t < KNN; t++) {
            float d = sbd[pt*KNN + t];
            if (!(d < bd[KNN-1])) break;
            topk_insert(bd, bi, d, sbi[pt*KNN + t]);
        }
        int gi = b * PP + il;
#pragma unroll
        for (int t = 0; t < KNN; t++) g_idx[gi*KNN + t] = b * PP + bi[t];
    }
}

// ---------------- EdgeConv1 v2: fused W01, persistent ----------------
#define C1_LDD 68
#define C1_LDW 72
__global__ __launch_bounds__(256, 2) void conv1_kernel(
    const float* __restrict__ pos,
    const float* __restrict__ w2, const float* __restrict__ b2)
{
    extern __shared__ float sm[];
    float* sW01 = sm;             // 8*72
    float* sW2  = sm + 576;       // 64*72
    float* sb01 = sm + 5184;      // 64
    float* sb2  = sm + 5248;      // 64
    float* sD   = sm + 5312;      // 160*68

    int tid = threadIdx.x, lane = tid & 31, warp = tid >> 5;
    int g4 = lane >> 2, tig = lane & 3;
    int wm = warp >> 2, wn = warp & 3;
    int mB = wm * 80, nB = wn * 16;

    for (int fi = tid; fi < 512; fi += 256) {
        int kk = fi >> 6, o = fi & 63;
        sW01[kk*C1_LDW + o] = (kk < 6) ? tfbits(g_w01[kk*64 + o]) : 0.f;
    }
    for (int fi = tid; fi < 4096; fi += 256) {
        int kk = fi >> 6, o = fi & 63;
        sW2[kk*C1_LDW + o] = tfbits(w2[fi]);
    }
    if (tid < 64) { sb01[tid] = g_b01[tid]; sb2[tid] = b2[tid]; }

    float acc[5][2][4];
    for (int g = blockIdx.x; g < 4096; g += gridDim.x) {
        int ibase = g * 8;
        __syncthreads();
        if (tid < 160) {
            int p = tid / 20, e = tid - p*20;
            int i = ibase + p;
            int j = g_idx[i*KNN + e];
            float xx = pos[i*3], xy = pos[i*3+1], xz = pos[i*3+2];
            float jx = pos[j*3], jy = pos[j*3+1], jz = pos[j*3+2];
            float* dr = sD + tid*C1_LDD;
            dr[0] = tfbits(xx); dr[1] = tfbits(xy); dr[2] = tfbits(xz);
            dr[3] = tfbits(jx-xx); dr[4] = tfbits(jy-xy); dr[5] = tfbits(jz-xz);
            dr[6] = 0.f; dr[7] = 0.f;
        }
        __syncthreads();
        mma_5x2(sD, sW01, acc, mB, nB, g4, tig, 1, C1_LDD, C1_LDW);
        __syncthreads();
        wb_5x2(sD, acc, sb01, mB, nB, g4, tig, C1_LDD, 1);
        __syncthreads();
        mma_5x2(sD, sW2, acc, mB, nB, g4, tig, 8, C1_LDD, C1_LDW);
        {
            float pm[4][2][2];
#pragma unroll
            for (int p = 0; p < 4; p++)
#pragma unroll
                for (int ni = 0; ni < 2; ni++) { pm[p][ni][0] = -3.4e38f; pm[p][ni][1] = -3.4e38f; }
            bool hi = (g4 >= 4);
#pragma unroll
            for (int ni = 0; ni < 2; ni++) {
                pm[0][ni][0] = fmaxf(pm[0][ni][0], acc[0][ni][0]);
                pm[0][ni][1] = fmaxf(pm[0][ni][1], acc[0][ni][1]);
                if (!hi) { pm[0][ni][0] = fmaxf(pm[0][ni][0], acc[1][ni][0]);
                           pm[0][ni][1] = fmaxf(pm[0][ni][1], acc[1][ni][1]); }
                else     { pm[1][ni][0] = fmaxf(pm[1][ni][0], acc[1][ni][0]);
                           pm[1][ni][1] = fmaxf(pm[1][ni][1], acc[1][ni][1]); }
                pm[1][ni][0] = fmaxf(pm[1][ni][0], acc[2][ni][0]);
                pm[1][ni][1] = fmaxf(pm[1][ni][1], acc[2][ni][1]);
                pm[2][ni][0] = fmaxf(pm[2][ni][0], acc[3][ni][0]);
                pm[2][ni][1] = fmaxf(pm[2][ni][1], acc[3][ni][1]);
                pm[3][ni][0] = fmaxf(pm[3][ni][0], acc[4][ni][0]);
                pm[3][ni][1] = fmaxf(pm[3][ni][1], acc[4][ni][1]);
                pm[0][ni][0] = fmaxf(pm[0][ni][0], acc[0][ni][2]);
                pm[0][ni][1] = fmaxf(pm[0][ni][1], acc[0][ni][3]);
                pm[1][ni][0] = fmaxf(pm[1][ni][0], acc[1][ni][2]);
                pm[1][ni][1] = fmaxf(pm[1][ni][1], acc[1][ni][3]);
                pm[2][ni][0] = fmaxf(pm[2][ni][0], acc[2][ni][2]);
                pm[2][ni][1] = fmaxf(pm[2][ni][1], acc[2][ni][3]);
                if (!hi) { pm[2][ni][0] = fmaxf(pm[2][ni][0], acc[3][ni][2]);
                           pm[2][ni][1] = fmaxf(pm[2][ni][1], acc[3][ni][3]); }
                else     { pm[3][ni][0] = fmaxf(pm[3][ni][0], acc[3][ni][2]);
                           pm[3][ni][1] = fmaxf(pm[3][ni][1], acc[3][ni][3]); }
                pm[3][ni][0] = fmaxf(pm[3][ni][0], acc[4][ni][2]);
                pm[3][ni][1] = fmaxf(pm[3][ni][1], acc[4][ni][3]);
            }
#pragma unroll
            for (int off = 4; off < 32; off <<= 1)
#pragma unroll
                for (int p = 0; p < 4; p++)
#pragma unroll
                    for (int ni = 0; ni < 2; ni++) {
                        pm[p][ni][0] = fmaxf(pm[p][ni][0], __shfl_xor_sync(0xffffffff, pm[p][ni][0], off));
                        pm[p][ni][1] = fmaxf(pm[p][ni][1], __shfl_xor_sync(0xffffffff, pm[p][ni][1], off));
                    }
            if (g4 == 0) {
#pragma unroll
                for (int p = 0; p < 4; p++) {
                    int wp = wm*4 + p;
#pragma unroll
                    for (int ni = 0; ni < 2; ni++) {
                        int col = nB + ni*8 + tig*2;
                        float2 o;
                        o.x = fmaxf(pm[p][ni][0] + sb2[col],   0.f);
                        o.y = fmaxf(pm[p][ni][1] + sb2[col+1], 0.f);
                        *(float2*)&g_x1[(size_t)(ibase+wp)*64 + col] = o;
                    }
                }
            }
        }
    }
}

// ---------------- KNN over 64-D features v4: split-scan selection (all 256 threads) ----------------
#define KF_LDA 68
__global__ __launch_bounds__(256, 2) void knn_feat_kernel()
{
    extern __shared__ float sm[];
    float* sA   = sm;                        // 128*68  (Xi tf32)
    float* sB   = sA + 128*KF_LDA;           // 64*68   (Xj tf32)
    float* sdot = sB + 64*KF_LDA;            // 128*68
    float* sqi  = sdot + 128*KF_LDA;         // 128
    float* sqj  = sqi + 128;                 // 64
    float* sbd  = sqj + 64;                  // 128*20
    int*   sbi  = (int*)(sbd + 128*KNN);     // 128*20

    int tid = threadIdx.x, lane = tid & 31, warp = tid >> 5;
    int g4 = lane >> 2, tig = lane & 3;
    int wm = warp >> 1, wn = warp & 1;       // 4 m-warps x 2 n-warps; tile 32x32
    int b = blockIdx.y;
    int i0 = b*PP + blockIdx.x*128;
    const float4* x1v = (const float4*)g_x1;

    for (int fi = tid; fi < 128*16; fi += 256) {
        int pt = fi >> 4, q = fi & 15;
        float4 v = x1v[(size_t)(i0+pt)*16 + q];
        *(float4*)&sA[pt*KF_LDA + q*4] =
            make_float4(tfbits(v.x), tfbits(v.y), tfbits(v.z), tfbits(v.w));
    }
    if (tid < 128) {
        float s = 0.f;
#pragma unroll
        for (int q = 0; q < 16; q++) {
            float4 v = x1v[(size_t)(i0+tid)*16 + q];
            s += v.x*v.x + v.y*v.y + v.z*v.z + v.w*v.w;
        }
        sqi[tid] = s;
    }

    int spt = tid & 127, ssc = tid >> 7;     // selection: point, scanner half
    float bd[KNN]; int bi[KNN];
#pragma unroll
    for (int t = 0; t < KNN; t++) { bd[t] = 3.4e38f; bi[t] = 0; }
    float mysq = 0.f;

    for (int jt = 0; jt < 16; jt++) {
        int j0 = b*PP + jt*64;
        __syncthreads();
#pragma unroll
        for (int r = 0; r < 4; r++) {
            int fi = tid + r*256;
            int pt = fi >> 4, q = fi & 15;
            float4 v = x1v[(size_t)(j0+pt)*16 + q];
            *(float4*)&sB[pt*KF_LDA + q*4] =
                make_float4(tfbits(v.x), tfbits(v.y), tfbits(v.z), tfbits(v.w));
        }
        if (tid < 64) {
            float s = 0.f;
#pragma unroll
            for (int q = 0; q < 16; q++) {
                float4 v = x1v[(size_t)(j0+tid)*16 + q];
                s += v.x*v.x + v.y*v.y + v.z*v.z + v.w*v.w;
            }
            sqj[tid] = s;
        }
        __syncthreads();
        // GEMM dot[128 i][64 j], K=64; warp tile 32x32
        float acc[2][4][4];
#pragma unroll
        for (int mi = 0; mi < 2; mi++)
#pragma unroll
            for (int ni = 0; ni < 4; ni++)
#pragma unroll
                for (int c = 0; c < 4; c++) acc[mi][ni][c] = 0.f;
#pragma unroll
        for (int ks = 0; ks < 8; ks++) {
            int k0 = ks*8;
            uint32_t A[2][4];
#pragma unroll
            for (int mi = 0; mi < 2; mi++) {
                int row = wm*32 + mi*16 + g4;
                A[mi][0] = __float_as_uint(sA[row*KF_LDA + k0 + tig]);
                A[mi][1] = __float_as_uint(sA[(row+8)*KF_LDA + k0 + tig]);
                A[mi][2] = __float_as_uint(sA[row*KF_LDA + k0 + tig + 4]);
                A[mi][3] = __float_as_uint(sA[(row+8)*KF_LDA + k0 + tig + 4]);
            }
            uint32_t Bf[4][2];
#pragma unroll
            for (int ni = 0; ni < 4; ni++) {
                int col = wn*32 + ni*8 + g4;
                Bf[ni][0] = __float_as_uint(sB[col*KF_LDA + k0 + tig]);
                Bf[ni][1] = __float_as_uint(sB[col*KF_LDA + k0 + tig + 4]);
            }
#pragma unroll
            for (int mi = 0; mi < 2; mi++)
#pragma unroll
                for (int ni = 0; ni < 4; ni++)
                    mma8(acc[mi][ni][0], acc[mi][ni][1], acc[mi][ni][2], acc[mi][ni][3],
                         A[mi][0], A[mi][1], A[mi][2], A[mi][3], Bf[ni][0], Bf[ni][1]);
        }
#pragma unroll
        for (int mi = 0; mi < 2; mi++) {
#pragma unroll
            for (int ni = 0; ni < 4; ni++) {
                int row = wm*32 + mi*16 + g4, col = wn*32 + ni*8 + tig*2;
                *(float2*)&sdot[row*KF_LDA + col]     = make_float2(acc[mi][ni][0], acc[mi][ni][1]);
                *(float2*)&sdot[(row+8)*KF_LDA + col] = make_float2(acc[mi][ni][2], acc[mi][ni][3]);
            }
        }
        __syncthreads();
        // split selection: scanner ssc covers j-cols [ssc*32, ssc*32+32)
        {
            if (jt == 0) mysq = sqi[spt];
            const float4* drow4 = (const float4*)(sdot + spt*KF_LDA) + ssc*8;
            const float4* sqj4  = (const float4*)sqj + ssc*8;
            int jbase = jt*64 + ssc*32;
#pragma unroll 4
            for (int j4 = 0; j4 < 8; j4++) {
                float4 dv = drow4[j4];
                float4 sv = sqj4[j4];
                float d0 = mysq + sv.x - 2.0f*dv.x;
                float d1 = mysq + sv.y - 2.0f*dv.y;
                float d2 = mysq + sv.z - 2.0f*dv.z;
                float d3 = mysq + sv.w - 2.0f*dv.w;
                float mn = fminf(fminf(d0, d1), fminf(d2, d3));
                if (mn < bd[KNN-1]) {
                    topk_insert(bd, bi, d0, jbase + 4*j4 + 0);
                    topk_insert(bd, bi, d1, jbase + 4*j4 + 1);
                    topk_insert(bd, bi, d2, jbase + 4*j4 + 2);
                    topk_insert(bd, bi, d3, jbase + 4*j4 + 3);
                }
            }
        }
    }
    __syncthreads();
    if (ssc == 1) {
#pragma unroll
        for (int t = 0; t < KNN; t++) { sbd[spt*KNN + t] = bd[t]; sbi[spt*KNN + t] = bi[t]; }
    }
    __syncthreads();
    if (ssc == 0) {
        for (int t = 0; t < KNN; t++) {
            float d = sbd[spt*KNN + t];
            if (!(d < bd[KNN-1])) break;
            topk_insert(bd, bi, d, sbi[spt*KNN + t]);
        }
        int gi = i0 + spt;
#pragma unroll
        for (int t = 0; t < KNN; t++) g_idx[(size_t)gi*KNN + t] = b*PP + bi[t];
    }
}

// ---------------- EdgeConv2 v6: persistent grid-stride + flat build + coop base + diff GEMM ----------------
#define C2_LDD 68
#define C2_LDW 136
#define C2_LDB 132
__global__ __launch_bounds__(256, 2) void conv2_kernel(
    const float* __restrict__ w, const float* __restrict__ bias)
{
    extern __shared__ float sm[];
    float* sWb   = sm;                        // 64*136
    float* sD    = sm + 64*C2_LDW;            // 160*68
    float* sXi   = sD + 160*C2_LDD;           // 8*68
    float* sBase = sXi + 8*68;                // 8*132
    float* sbias = sBase + 8*C2_LDB;          // 128
    int*   sJ    = (int*)(sbias + 128);       // 160
    int*   sP    = sJ + 160;                  // 160

    int tid = threadIdx.x, lane = tid & 31, warp = tid >> 5;
    int g4 = lane >> 2, tig = lane & 3;
    int wm = warp >> 2, wn = warp & 3;
    int mB = wm*80, nB = wn*32;

    for (int fi = tid; fi < 2048; fi += 256) {
        int kk = fi >> 5, nq = fi & 31;
        float4 v = ((const float4*)w)[(64+kk)*32 + nq];
        *(float4*)&sWb[kk*C2_LDW + nq*4] =
            make_float4(tfbits(v.x), tfbits(v.y), tfbits(v.z), tfbits(v.w));
    }
    if (tid < 128) sbias[tid] = bias[tid];

    const float4* x1v = (const float4*)g_x1;

    for (int g = blockIdx.x; g < 4096; g += gridDim.x) {
        int ibase = g * 8;
        __syncthreads();
        if (tid < 128) {
            int p = tid >> 4, q = tid & 15;
            *(float4*)&sXi[p*68 + q*4] = x1v[(size_t)(ibase+p)*16 + q];
        }
        if (tid < 160) {
            int p = tid / 20;
            sJ[tid] = g_idx[(size_t)(ibase+p)*KNN + (tid - p*20)];
            sP[tid] = p;
        }
        __syncthreads();
#pragma unroll
        for (int it = 0; it < 10; it++) {
            int fi = tid + it*256;
            int row = fi >> 4, q = fi & 15;
            int j = sJ[row], p = sP[row];
            float4 xj = x1v[(size_t)j*16 + q];
            float4 xi = *(const float4*)&sXi[p*68 + q*4];
            *(float4*)&sD[row*C2_LDD + q*4] =
                make_float4(tfbits(xj.x-xi.x), tfbits(xj.y-xi.y),
                            tfbits(xj.z-xi.z), tfbits(xj.w-xi.w));
        }
        {
            int p = lane >> 2, c4 = lane & 3;
            int colq = warp*4 + c4;
            const float* xir = &sXi[p*68];
            float4 acc4 = ((const float4*)sbias)[colq];
#pragma unroll 8
            for (int k = 0; k < 64; k++) {
                float xv = xir[k];
                float4 wv = ((const float4*)w)[k*32 + colq];
                acc4.x = fmaf(xv, wv.x, acc4.x); acc4.y = fmaf(xv, wv.y, acc4.y);
                acc4.z = fmaf(xv, wv.z, acc4.z); acc4.w = fmaf(xv, wv.w, acc4.w);
            }
            *(float4*)&sBase[p*C2_LDB + colq*4] = acc4;
        }
        __syncthreads();
        float acc[5][4][4];
#pragma unroll
        for (int mi = 0; mi < 5; mi++)
#pragma unroll
            for (int ni = 0; ni < 4; ni++)
#pragma unroll
                for (int c = 0; c < 4; c++) acc[mi][ni][c] = 0.f;
#pragma unroll 1
        for (int ks = 0; ks < 8; ks++) {
            int k0 = ks*8;
            uint32_t A[5][4];
#pragma unroll
            for (int mi = 0; mi < 5; mi++) {
                int row = mB + mi*16 + g4;
                A[mi][0] = __float_as_uint(sD[row*C2_LDD + k0 + tig]);
                A[mi][1] = __float_as_uint(sD[(row+8)*C2_LDD + k0 + tig]);
                A[mi][2] = __float_as_uint(sD[row*C2_LDD + k0 + tig + 4]);
                A[mi][3] = __float_as_uint(sD[(row+8)*C2_LDD + k0 + tig + 4]);
            }
            uint32_t Bf[4][2];
#pragma unroll
            for (int ni = 0; ni < 4; ni++) {
                int col = nB + ni*8 + g4;
                Bf[ni][0] = __float_as_uint(sWb[(k0+tig)*C2_LDW + col]);
                Bf[ni][1] = __float_as_uint(sWb[(k0+tig+4)*C2_LDW + col]);
            }
#pragma unroll
            for (int mi = 0; mi < 5; mi++)
#pragma unroll
                for (int ni = 0; ni < 4; ni++)
                    mma8(acc[mi][ni][0], acc[mi][ni][1], acc[mi][ni][2], acc[mi][ni][3],
                         A[mi][0], A[mi][1], A[mi][2], A[mi][3], Bf[ni][0], Bf[ni][1]);
        }
        float pm[4][4][2];
#pragma unroll
        for (int p = 0; p < 4; p++)
#pragma unroll
            for (int ni = 0; ni < 4; ni++) { pm[p][ni][0] = -3.4e38f; pm[p][ni][1] = -3.4e38f; }
        bool hi = (g4 >= 4);
#pragma unroll
        for (int ni = 0; ni < 4; ni++) {
            pm[0][ni][0] = fmaxf(pm[0][ni][0], acc[0][ni][0]);
            pm[0][ni][1] = fmaxf(pm[0][ni][1], acc[0][ni][1]);
            if (!hi) { pm[0][ni][0] = fmaxf(pm[0][ni][0], acc[1][ni][0]);
                       pm[0][ni][1] = fmaxf(pm[0][ni][1], acc[1][ni][1]); }
            else     { pm[1][ni][0] = fmaxf(pm[1][ni][0], acc[1][ni][0]);
                       pm[1][ni][1] = fmaxf(pm[1][ni][1], acc[1][ni][1]); }
            pm[1][ni][0] = fmaxf(pm[1][ni][0], acc[2][ni][0]);
            pm[1][ni][1] = fmaxf(pm[1][ni][1], acc[2][ni][1]);
            pm[2][ni][0] = fmaxf(pm[2][ni][0], acc[3][ni][0]);
            pm[2][ni][1] = fmaxf(pm[2][ni][1], acc[3][ni][1]);
            pm[3][ni][0] = fmaxf(pm[3][ni][0], acc[4][ni][0]);
            pm[3][ni][1] = fmaxf(pm[3][ni][1], acc[4][ni][1]);
            pm[0][ni][0] = fmaxf(pm[0][ni][0], acc[0][ni][2]);
            pm[0][ni][1] = fmaxf(pm[0][ni][1], acc[0][ni][3]);
            pm[1][ni][0] = fmaxf(pm[1][ni][0], acc[1][ni][2]);
            pm[1][ni][1] = fmaxf(pm[1][ni][1], acc[1][ni][3]);
            pm[2][ni][0] = fmaxf(pm[2][ni][0], acc[2][ni][2]);
            pm[2][ni][1] = fmaxf(pm[2][ni][1], acc[2][ni][3]);
            if (!hi) { pm[2][ni][0] = fmaxf(pm[2][ni][0], acc[3][ni][2]);
                       pm[2][ni][1] = fmaxf(pm[2][ni][1], acc[3][ni][3]); }
            else     { pm[3][ni][0] = fmaxf(pm[3][ni][0], acc[3][ni][2]);
                       pm[3][ni][1] = fmaxf(pm[3][ni][1], acc[3][ni][3]); }
            pm[3][ni][0] = fmaxf(pm[3][ni][0], acc[4][ni][2]);
            pm[3][ni][1] = fmaxf(pm[3][ni][1], acc[4][ni][3]);
        }
#pragma unroll
        for (int off = 4; off < 32; off <<= 1)
#pragma unroll
            for (int p = 0; p < 4; p++)
#pragma unroll
                for (int ni = 0; ni < 4; ni++) {
                    pm[p][ni][0] = fmaxf(pm[p][ni][0], __shfl_xor_sync(0xffffffff, pm[p][ni][0], off));
                    pm[p][ni][1] = fmaxf(pm[p][ni][1], __shfl_xor_sync(0xffffffff, pm[p][ni][1], off));
                }
        if (g4 == 0) {
#pragma unroll
            for (int p = 0; p < 4; p++) {
                int wp = wm*4 + p;
#pragma unroll
                for (int ni = 0; ni < 4; ni++) {
                    int col = nB + ni*8 + tig*2;
                    float b0v = sBase[wp*C2_LDB + col];
                    float b1v = sBase[wp*C2_LDB + col + 1];
                    float2 o;
                    o.x = fmaxf(pm[p][ni][0] + b0v, 0.f);
                    o.y = fmaxf(pm[p][ni][1] + b1v, 0.f);
                    *(float2*)&g_x2[(size_t)(ibase+wp)*128 + col] = o;
                }
            }
        }
    }
}

// ---------------- l1 (192->1024) tf32 GEMM, k-chunk 32, + fused relu + P-max ----------------
#define L1_LDA 36
__global__ __launch_bounds__(256) void l1max_kernel(
    const float* __restrict__ w, const float* __restrict__ bias)
{
    __shared__ float sA[128*L1_LDA];
    __shared__ float sB[32*136];
    __shared__ float sbias[128];
    __shared__ unsigned int sred[128];
    int tid = threadIdx.x;
    int lane = tid & 31, warp = tid >> 5;
    int g4 = lane >> 2, tig = lane & 3;
    int b = blockIdx.z;
    int n0 = blockIdx.x * 128, m0 = blockIdx.y * 128;
    int pbase = b * PP + m0;
    const float4* x1v = (const float4*)g_x1;
    const float4* x2v = (const float4*)g_x2;
    const float4* wv  = (const float4*)w;
    if (tid < 128) { sred[tid] = 0u; sbias[tid] = bias[n0 + tid]; }

    int wm = warp >> 2, wn = warp & 3;
    float acc[4][4][4];
#pragma unroll
    for (int mi = 0; mi < 4; mi++)
#pragma unroll
        for (int ni = 0; ni < 4; ni++)
#pragma unroll
            for (int c = 0; c < 4; c++) acc[mi][ni][c] = 0.f;

    for (int ks = 0; ks < 6; ks++) {
        __syncthreads();
#pragma unroll
        for (int r = 0; r < 4; r++) {
            int fi = tid + r*256;
            int pt = fi >> 3, kq = fi & 7;
            float4 v = (ks < 2) ? x1v[(size_t)(pbase+pt)*16 + ks*8 + kq]
                                : x2v[(size_t)(pbase+pt)*32 + (ks-2)*8 + kq];
            *(float4*)&sA[pt*L1_LDA + kq*4] =
                make_float4(tfbits(v.x), tfbits(v.y), tfbits(v.z), tfbits(v.w));
        }
#pragma unroll
        for (int r = 0; r < 4; r++) {
            int fi = tid + r*256;
            int kk = fi >> 5, nq = fi & 31;
            float4 v = wv[(size_t)(ks*32+kk)*256 + (n0>>2) + nq];
            *(float4*)&sB[kk*136 + nq*4] =
                make_float4(tfbits(v.x), tfbits(v.y), tfbits(v.z), tfbits(v.w));
        }
        __syncthreads();
#pragma unroll
        for (int kh = 0; kh < 4; kh++) {
            int k0 = kh*8;
            uint32_t A[4][4];
#pragma unroll
            for (int mi = 0; mi < 4; mi++) {
                int row = wm*64 + mi*16 + g4;
                A[mi][0] = __float_as_uint(sA[row*L1_LDA + k0 + tig]);
                A[mi][1] = __float_as_uint(sA[(row+8)*L1_LDA + k0 + tig]);
                A[mi][2] = __float_as_uint(sA[row*L1_LDA + k0 + tig + 4]);
                A[mi][3] = __float_as_uint(sA[(row+8)*L1_LDA + k0 + tig + 4]);
            }
            uint32_t Bf[4][2];
#pragma unroll
            for (int ni = 0; ni < 4; ni++) {
                int col = wn*32 + ni*8 + g4;
                Bf[ni][0] = __float_as_uint(sB[(k0+tig)*136 + col]);
                Bf[ni][1] = __float_as_uint(sB[(k0+tig+4)*136 + col]);
            }
#pragma unroll
            for (int mi = 0; mi < 4; mi++)
#pragma unroll
                for (int ni = 0; ni < 4; ni++)
                    mma8(acc[mi][ni][0], acc[mi][ni][1], acc[mi][ni][2], acc[mi][ni][3],
                         A[mi][0], A[mi][1], A[mi][2], A[mi][3], Bf[ni][0], Bf[ni][1]);
        }
    }
#pragma unroll
    for (int ni = 0; ni < 4; ni++) {
        float v0 = -3.4e38f, v1 = -3.4e38f;
#pragma unroll
        for (int mi = 0; mi < 4; mi++) {
            v0 = fmaxf(v0, fmaxf(acc[mi][ni][0], acc[mi][ni][2]));
            v1 = fmaxf(v1, fmaxf(acc[mi][ni][1], acc[mi][ni][3]));
        }
#pragma unroll
        for (int off = 4; off < 32; off <<= 1) {
            v0 = fmaxf(v0, __shfl_xor_sync(0xffffffff, v0, off));
            v1 = fmaxf(v1, __shfl_xor_sync(0xffffffff, v1, off));
        }
        if (g4 == 0) {
            int col = wn*32 + ni*8 + tig*2;
            float a0 = fmaxf(v0 + sbias[col], 0.f);
            float a1 = fmaxf(v1 + sbias[col+1], 0.f);
            atomicMax(&sred[col],   __float_as_uint(a0));
            atomicMax(&sred[col+1], __float_as_uint(a1));
        }
    }
    __syncthreads();
    if (tid < 128) atomicMax(&g_pool[b*1024 + n0 + tid], sred[tid]);
}

// ---------------- head0: h0 = relu(pool @ m_w0 + b0), grid (2, 32) ----------------
__global__ __launch_bounds__(256) void head0_kernel(
    const float* __restrict__ w0, const float* __restrict__ b0)
{
    __shared__ float sp[1024];
    int b = blockIdx.y, tid = threadIdx.x;
    int o = blockIdx.x * 256 + tid;
    for (int c = tid; c < 1024; c += 256) sp[c] = __uint_as_float(g_pool[b*1024 + c]);
    __syncthreads();
    float a0 = 0.f, a1 = 0.f, a2 = 0.f, a3 = 0.f;
    for (int c = 0; c < 1024; c += 4) {
        a0 = fmaf(sp[c+0], w0[(size_t)(c+0)*512 + o], a0);
        a1 = fmaf(sp[c+1], w0[(size_t)(c+1)*512 + o], a1);
        a2 = fmaf(sp[c+2], w0[(size_t)(c+2)*512 + o], a2);
        a3 = fmaf(sp[c+3], w0[(size_t)(c+3)*512 + o], a3);
    }
    g_h0[b*512 + o] = fmaxf(((a0 + a1) + (a2 + a3)) + b0[o], 0.f);
}

// ---------------- head1: 512->256 relu ->40 + log_softmax, grid 32 ----------------
__global__ __launch_bounds__(256) void head1_kernel(
    const float* __restrict__ w1, const float* __restrict__ b1,
    const float* __restrict__ w2, const float* __restrict__ b2,
    float* __restrict__ out)
{
    __shared__ float sh0[512], sh1[256], sl[40], red[2];
    int b = blockIdx.x, tid = threadIdx.x;
    for (int c = tid; c < 512; c += 256) sh0[c] = g_h0[b*512 + c];
    __syncthreads();
    {
        float a0 = 0.f, a1 = 0.f;
        for (int c = 0; c < 512; c += 2) {
            a0 = fmaf(sh0[c],   w1[(size_t)c*256 + tid],     a0);
            a1 = fmaf(sh0[c+1], w1[(size_t)(c+1)*256 + tid], a1);
        }
        sh1[tid] = fmaxf(a0 + a1 + b1[tid], 0.f);
    }
    __syncthreads();
    if (tid < 40) {
        float a = b2[tid];
        for (int c = 0; c < 256; c++) a += sh1[c] * w2[c*40 + tid];
        sl[tid] = a;
    }
    __syncthreads();
    if (tid == 0) {
        float mxv = -3.4e38f;
        for (int t = 0; t < 40; t++) mxv = fmaxf(mxv, sl[t]);
        float s = 0.f;
        for (int t = 0; t < 40; t++) s += expf(sl[t] - mxv);
        red[0] = mxv; red[1] = logf(s);
    }
    __syncthreads();
    if (tid < 40) out[b*40 + tid] = sl[tid] - red[0] - red[1];
}

// ---------------- launch ----------------
extern "C" void kernel_launch(void* const* d_in, const int* in_sizes, int n_in,
                              void* d_out, int out_size)
{
    const float* pos   = (const float*)d_in[0];
    const float* c1_w0 = (const float*)d_in[2];
    const float* c1_b0 = (const float*)d_in[3];
    const float* c1_w1 = (const float*)d_in[4];
    const float* c1_b1 = (const float*)d_in[5];
    const float* c1_w2 = (const float*)d_in[6];
    const float* c1_b2 = (const float*)d_in[7];
    const float* c2_w0 = (const float*)d_in[8];
    const float* c2_b0 = (const float*)d_in[9];
    const float* l1_w  = (const float*)d_in[10];
    const float* l1_b  = (const float*)d_in[11];
    const float* m_w0  = (const float*)d_in[12];
    const float* m_b0  = (const float*)d_in[13];
    const float* m_w1  = (const float*)d_in[14];
    const float* m_b1  = (const float*)d_in[15];
    const float* m_w2  = (const float*)d_in[16];
    const float* m_b2  = (const float*)d_in[17];
    float* out = (float*)d_out;

    const int smem_kpos  = 4096*4 + 5120*4 + 5120*4;                                     // 57344
    const int smem_conv1 = (576 + 4608 + 128 + 160*C1_LDD) * 4;                          // 64768
    const int smem_knn2  = (128*KF_LDA + 64*KF_LDA + 128*KF_LDA + 128 + 64
                            + 128*KNN + 128*KNN) * 4;                                     // 108288
    const int smem_conv2 = (64*C2_LDW + 160*C2_LDD + 8*68 + 8*C2_LDB + 128 + 320) * 4;   // ~86.5 KB

    cudaFuncSetAttribute(knn_pos_kernel,  cudaFuncAttributeMaxDynamicSharedMemorySize, smem_kpos);
    cudaFuncSetAttribute(conv1_kernel,    cudaFuncAttributeMaxDynamicSharedMemorySize, smem_conv1);
    cudaFuncSetAttribute(knn_feat_kernel, cudaFuncAttributeMaxDynamicSharedMemorySize, smem_knn2);
    cudaFuncSetAttribute(conv2_kernel,    cudaFuncAttributeMaxDynamicSharedMemorySize, smem_conv2);

    fuse_w01_kernel<<<1, 512>>>(c1_w0, c1_b0, c1_w1, c1_b1);
    knn_pos_kernel<<<dim3(4, 32), 512, smem_kpos>>>(pos);
    conv1_kernel<<<296, 256, smem_conv1>>>(pos, c1_w2, c1_b2);
    knn_feat_kernel<<<dim3(8, 32), 256, smem_knn2>>>();
    conv2_kernel<<<296, 256, smem_conv2>>>(c2_w0, c2_b0);
    l1max_kernel<<<dim3(8, 8, 32), 256>>>(l1_w, l1_b);
    head0_kernel<<<dim3(2, 32), 256>>>(m_w0, m_b0);
    head1_kernel<<<32, 256>>>(m_w1, m_b1, m_w2, m_b2, out);
}

// round 14
// speedup vs baseline: 10.6211x; 10.6211x over previous
#include <cuda_runtime.h>
#include <math.h>
#include <stdint.h>

#define BB 32
#define PP 1024
#define KNN 20
#define NPTS (BB*PP)

// ---------------- scratch (device globals; no allocs allowed) ----------------
__device__ __align__(16) float g_x1[NPTS*64];
__device__ __align__(16) float g_x2[NPTS*128];
__device__ int g_idx[NPTS*KNN];
__device__ unsigned int g_pool[BB*1024];
__device__ __align__(16) float g_h0[BB*512];
__device__ __align__(16) float g_w01[8*64];
__device__ __align__(16) float g_b01[64];

// ---------------- tf32 mma helpers ----------------
__device__ __forceinline__ uint32_t f2tf(float x) {
    uint32_t r; asm("cvt.rna.tf32.f32 %0, %1;" : "=r"(r) : "f"(x)); return r;
}
__device__ __forceinline__ float tfbits(float x) {
    return __uint_as_float(f2tf(x));
}
__device__ __forceinline__ void mma8(float& c0, float& c1, float& c2, float& c3,
                                     uint32_t a0, uint32_t a1, uint32_t a2, uint32_t a3,
                                     uint32_t b0, uint32_t b1)
{
    asm volatile("mma.sync.aligned.m16n8k8.row.col.f32.tf32.tf32.f32 "
                 "{%0,%1,%2,%3},{%4,%5,%6,%7},{%8,%9},{%0,%1,%2,%3};"
                 : "+f"(c0), "+f"(c1), "+f"(c2), "+f"(c3)
                 : "r"(a0), "r"(a1), "r"(a2), "r"(a3), "r"(b0), "r"(b1));
}

// Unsorted top-k buffer with tracked worst value/slot. All indices static
// (full unroll + cmov) so arrays stay in registers. Downstream use of the
// neighbor list is permutation-invariant (gather + max), so order is free.
// Strict < gate keeps first-seen (lowest j); >= in argmax evicts the
// later-inserted among equal-worst — matches jax tie semantics.
__device__ __forceinline__ void tk_ins(float* bd, int* bi, float& worst, int& wslot,
                                       float d, int j)
{
    if (d < worst) {
        bd[wslot] = d; bi[wslot] = j;
        float w = bd[0]; int ws = 0;
#pragma unroll
        for (int t = 1; t < KNN; t++) {
            bool g = bd[t] >= w;
            w  = g ? bd[t] : w;
            ws = g ? t : ws;
        }
        worst = w; wslot = ws;
    }
}

// 5 m-tiles x 2 n-tiles warp GEMM (used by conv1)
__device__ __forceinline__ void mma_5x2(
    const float* sD, const float* sW, float acc[5][2][4],
    int mB, int nB, int g4, int tig, int ksteps, int ldd, int ldw)
{
#pragma unroll
    for (int mi = 0; mi < 5; mi++)
#pragma unroll
        for (int ni = 0; ni < 2; ni++)
#pragma unroll
            for (int c = 0; c < 4; c++) acc[mi][ni][c] = 0.f;
#pragma unroll 1
    for (int ks = 0; ks < ksteps; ks++) {
        int k0 = ks * 8;
        uint32_t A[5][4];
#pragma unroll
        for (int mi = 0; mi < 5; mi++) {
            int row = mB + mi*16 + g4;
            A[mi][0] = __float_as_uint(sD[row*ldd + k0 + tig]);
            A[mi][1] = __float_as_uint(sD[(row+8)*ldd + k0 + tig]);
            A[mi][2] = __float_as_uint(sD[row*ldd + k0 + tig + 4]);
            A[mi][3] = __float_as_uint(sD[(row+8)*ldd + k0 + tig + 4]);
        }
        uint32_t Bf[2][2];
#pragma unroll
        for (int ni = 0; ni < 2; ni++) {
            int col = nB + ni*8 + g4;
            Bf[ni][0] = __float_as_uint(sW[(k0+tig)*ldw + col]);
            Bf[ni][1] = __float_as_uint(sW[(k0+tig+4)*ldw + col]);
        }
#pragma unroll
        for (int mi = 0; mi < 5; mi++)
#pragma unroll
            for (int ni = 0; ni < 2; ni++)
                mma8(acc[mi][ni][0], acc[mi][ni][1], acc[mi][ni][2], acc[mi][ni][3],
                     A[mi][0], A[mi][1], A[mi][2], A[mi][3], Bf[ni][0], Bf[ni][1]);
    }
}

__device__ __forceinline__ void wb_5x2(
    float* sD, float acc[5][2][4], const float* bias,
    int mB, int nB, int g4, int tig, int ldd, int mode)
{
#pragma unroll
    for (int mi = 0; mi < 5; mi++) {
#pragma unroll
        for (int ni = 0; ni < 2; ni++) {
            int row = mB + mi*16 + g4, col = nB + ni*8 + tig*2;
            float v0 = acc[mi][ni][0], v1 = acc[mi][ni][1];
            float v2 = acc[mi][ni][2], v3 = acc[mi][ni][3];
            float ba = bias[col], bb = bias[col+1];
            v0 += ba; v1 += bb; v2 += ba; v3 += bb;
            if (mode == 1) {
                v0 = fmaxf(v0, 0.f); v1 = fmaxf(v1, 0.f);
                v2 = fmaxf(v2, 0.f); v3 = fmaxf(v3, 0.f);
            }
            v0 = tfbits(v0); v1 = tfbits(v1); v2 = tfbits(v2); v3 = tfbits(v3);
            sD[row*ldd + col] = v0;     sD[row*ldd + col + 1] = v1;
            sD[(row+8)*ldd + col] = v2; sD[(row+8)*ldd + col + 1] = v3;
        }
    }
}

// ---------------- prologue: W01 = W0 @ W1, b01 = b0 @ W1 + b1 (exact fp32) ----------------
__global__ __launch_bounds__(512) void fuse_w01_kernel(
    const float* __restrict__ w0, const float* __restrict__ b0,
    const float* __restrict__ w1, const float* __restrict__ b1)
{
    int tid = threadIdx.x;
    if (tid < 384) {
        int c = tid >> 6, o = tid & 63;
        float s = 0.f;
        for (int h = 0; h < 64; h++) s = fmaf(w0[c*64 + h], w1[h*64 + o], s);
        g_w01[c*64 + o] = s;
    } else if (tid < 448) {
        int o = tid - 384;
        float s = b1[o];
        for (int h = 0; h < 64; h++) s = fmaf(b0[h], w1[h*64 + o], s);
        g_b01[o] = s;
    }
}

// ---------------- KNN over 3-D positions: split-scan (2 threads/point) + pool zero ----------------
__global__ __launch_bounds__(512) void knn_pos_kernel(const float* __restrict__ pos)
{
    extern __shared__ float smk[];
    float4* spos = (float4*)smk;                     // 1024 float4
    float*  sbd  = smk + 4096;                       // 256*20
    int*    sbi  = (int*)(smk + 4096 + 5120);        // 256*20
    int tid = threadIdx.x;
    int lb = blockIdx.y*4 + blockIdx.x;
    if (tid < 256) g_pool[lb*256 + tid] = 0u;
    int b = blockIdx.y;
    const float* p = pos + (size_t)b * PP * 3;
    for (int j = tid; j < PP; j += 512) {
        float x = p[3*j], y = p[3*j+1], z = p[3*j+2];
        spos[j] = make_float4(x, y, z, x*x + y*y + z*z);
    }
    __syncthreads();
    int pt = tid & 255, s = tid >> 8;
    int il = blockIdx.x * 256 + pt;
    float4 me = spos[il];
    float xi = me.x, yi = me.y, zi = me.z, sqi = me.w;
    float bd[KNN]; int bi[KNN];
    float worst = 3.4e38f; int wslot = 0;
#pragma unroll
    for (int t = 0; t < KNN; t++) { bd[t] = 3.4e38f; bi[t] = 0; }
    int j4base = s * 128;
    for (int j4 = j4base; j4 < j4base + 128; j4++) {
        float4 v0 = spos[4*j4+0], v1 = spos[4*j4+1], v2 = spos[4*j4+2], v3 = spos[4*j4+3];
        float d0 = sqi + v0.w - 2.0f*(xi*v0.x + yi*v0.y + zi*v0.z);
        float d1 = sqi + v1.w - 2.0f*(xi*v1.x + yi*v1.y + zi*v1.z);
        float d2 = sqi + v2.w - 2.0f*(xi*v2.x + yi*v2.y + zi*v2.z);
        float d3 = sqi + v3.w - 2.0f*(xi*v3.x + yi*v3.y + zi*v3.z);
        float mn = fminf(fminf(d0, d1), fminf(d2, d3));
        if (mn < worst) {
            tk_ins(bd, bi, worst, wslot, d0, 4*j4+0);
            tk_ins(bd, bi, worst, wslot, d1, 4*j4+1);
            tk_ins(bd, bi, worst, wslot, d2, 4*j4+2);
            tk_ins(bd, bi, worst, wslot, d3, 4*j4+3);
        }
    }
    if (s == 1) {
#pragma unroll
        for (int t = 0; t < KNN; t++) { sbd[pt*KNN + t] = bd[t]; sbi[pt*KNN + t] = bi[t]; }
    }
    __syncthreads();
    if (s == 0) {
#pragma unroll
        for (int t = 0; t < KNN; t++)
            tk_ins(bd, bi, worst, wslot, sbd[pt*KNN + t], sbi[pt*KNN + t]);
        int gi = b * PP + il;
#pragma unroll
        for (int t = 0; t < KNN; t++) g_idx[gi*KNN + t] = b * PP + bi[t];
    }
}

// ---------------- EdgeConv1 v2: fused W01, persistent ----------------
#define C1_LDD 68
#define C1_LDW 72
__global__ __launch_bounds__(256, 2) void conv1_kernel(
    const float* __restrict__ pos,
    const float* __restrict__ w2, const float* __restrict__ b2)
{
    extern __shared__ float sm[];
    float* sW01 = sm;             // 8*72
    float* sW2  = sm + 576;       // 64*72
    float* sb01 = sm + 5184;      // 64
    float* sb2  = sm + 5248;      // 64
    float* sD   = sm + 5312;      // 160*68

    int tid = threadIdx.x, lane = tid & 31, warp = tid >> 5;
    int g4 = lane >> 2, tig = lane & 3;
    int wm = warp >> 2, wn = warp & 3;
    int mB = wm * 80, nB = wn * 16;

    for (int fi = tid; fi < 512; fi += 256) {
        int kk = fi >> 6, o = fi & 63;
        sW01[kk*C1_LDW + o] = (kk < 6) ? tfbits(g_w01[kk*64 + o]) : 0.f;
    }
    for (int fi = tid; fi < 4096; fi += 256) {
        int kk = fi >> 6, o = fi & 63;
        sW2[kk*C1_LDW + o] = tfbits(w2[fi]);
    }
    if (tid < 64) { sb01[tid] = g_b01[tid]; sb2[tid] = b2[tid]; }

    float acc[5][2][4];
    for (int g = blockIdx.x; g < 4096; g += gridDim.x) {
        int ibase = g * 8;
        __syncthreads();
        if (tid < 160) {
            int p = tid / 20, e = tid - p*20;
            int i = ibase + p;
            int j = g_idx[i*KNN + e];
            float xx = pos[i*3], xy = pos[i*3+1], xz = pos[i*3+2];
            float jx = pos[j*3], jy = pos[j*3+1], jz = pos[j*3+2];
            float* dr = sD + tid*C1_LDD;
            dr[0] = tfbits(xx); dr[1] = tfbits(xy); dr[2] = tfbits(xz);
            dr[3] = tfbits(jx-xx); dr[4] = tfbits(jy-xy); dr[5] = tfbits(jz-xz);
            dr[6] = 0.f; dr[7] = 0.f;
        }
        __syncthreads();
        mma_5x2(sD, sW01, acc, mB, nB, g4, tig, 1, C1_LDD, C1_LDW);
        __syncthreads();
        wb_5x2(sD, acc, sb01, mB, nB, g4, tig, C1_LDD, 1);
        __syncthreads();
        mma_5x2(sD, sW2, acc, mB, nB, g4, tig, 8, C1_LDD, C1_LDW);
        {
            float pm[4][2][2];
#pragma unroll
            for (int p = 0; p < 4; p++)
#pragma unroll
                for (int ni = 0; ni < 2; ni++) { pm[p][ni][0] = -3.4e38f; pm[p][ni][1] = -3.4e38f; }
            bool hi = (g4 >= 4);
#pragma unroll
            for (int ni = 0; ni < 2; ni++) {
                pm[0][ni][0] = fmaxf(pm[0][ni][0], acc[0][ni][0]);
                pm[0][ni][1] = fmaxf(pm[0][ni][1], acc[0][ni][1]);
                if (!hi) { pm[0][ni][0] = fmaxf(pm[0][ni][0], acc[1][ni][0]);
                           pm[0][ni][1] = fmaxf(pm[0][ni][1], acc[1][ni][1]); }
                else     { pm[1][ni][0] = fmaxf(pm[1][ni][0], acc[1][ni][0]);
                           pm[1][ni][1] = fmaxf(pm[1][ni][1], acc[1][ni][1]); }
                pm[1][ni][0] = fmaxf(pm[1][ni][0], acc[2][ni][0]);
                pm[1][ni][1] = fmaxf(pm[1][ni][1], acc[2][ni][1]);
                pm[2][ni][0] = fmaxf(pm[2][ni][0], acc[3][ni][0]);
                pm[2][ni][1] = fmaxf(pm[2][ni][1], acc[3][ni][1]);
                pm[3][ni][0] = fmaxf(pm[3][ni][0], acc[4][ni][0]);
                pm[3][ni][1] = fmaxf(pm[3][ni][1], acc[4][ni][1]);
                pm[0][ni][0] = fmaxf(pm[0][ni][0], acc[0][ni][2]);
                pm[0][ni][1] = fmaxf(pm[0][ni][1], acc[0][ni][3]);
                pm[1][ni][0] = fmaxf(pm[1][ni][0], acc[1][ni][2]);
                pm[1][ni][1] = fmaxf(pm[1][ni][1], acc[1][ni][3]);
                pm[2][ni][0] = fmaxf(pm[2][ni][0], acc[2][ni][2]);
                pm[2][ni][1] = fmaxf(pm[2][ni][1], acc[2][ni][3]);
                if (!hi) { pm[2][ni][0] = fmaxf(pm[2][ni][0], acc[3][ni][2]);
                           pm[2][ni][1] = fmaxf(pm[2][ni][1], acc[3][ni][3]); }
                else     { pm[3][ni][0] = fmaxf(pm[3][ni][0], acc[3][ni][2]);
                           pm[3][ni][1] = fmaxf(pm[3][ni][1], acc[3][ni][3]); }
                pm[3][ni][0] = fmaxf(pm[3][ni][0], acc[4][ni][2]);
                pm[3][ni][1] = fmaxf(pm[3][ni][1], acc[4][ni][3]);
            }
#pragma unroll
            for (int off = 4; off < 32; off <<= 1)
#pragma unroll
                for (int p = 0; p < 4; p++)
#pragma unroll
                    for (int ni = 0; ni < 2; ni++) {
                        pm[p][ni][0] = fmaxf(pm[p][ni][0], __shfl_xor_sync(0xffffffff, pm[p][ni][0], off));
                        pm[p][ni][1] = fmaxf(pm[p][ni][1], __shfl_xor_sync(0xffffffff, pm[p][ni][1], off));
                    }
            if (g4 == 0) {
#pragma unroll
                for (int p = 0; p < 4; p++) {
                    int wp = wm*4 + p;
#pragma unroll
                    for (int ni = 0; ni < 2; ni++) {
                        int col = nB + ni*8 + tig*2;
                        float2 o;
                        o.x = fmaxf(pm[p][ni][0] + sb2[col],   0.f);
                        o.y = fmaxf(pm[p][ni][1] + sb2[col+1], 0.f);
                        *(float2*)&g_x1[(size_t)(ibase+wp)*64 + col] = o;
                    }
                }
            }
        }
    }
}

// ---------------- KNN over 64-D features v4: split-scan selection (all 256 threads) ----------------
#define KF_LDA 68
__global__ __launch_bounds__(256, 2) void knn_feat_kernel()
{
    extern __shared__ float sm[];
    float* sA   = sm;                        // 128*68  (Xi tf32)
    float* sB   = sA + 128*KF_LDA;           // 64*68   (Xj tf32)
    float* sdot = sB + 64*KF_LDA;            // 128*68
    float* sqi  = sdot + 128*KF_LDA;         // 128
    float* sqj  = sqi + 128;                 // 64
    float* sbd  = sqj + 64;                  // 128*20
    int*   sbi  = (int*)(sbd + 128*KNN);     // 128*20

    int tid = threadIdx.x, lane = tid & 31, warp = tid >> 5;
    int g4 = lane >> 2, tig = lane & 3;
    int wm = warp >> 1, wn = warp & 1;       // 4 m-warps x 2 n-warps; tile 32x32
    int b = blockIdx.y;
    int i0 = b*PP + blockIdx.x*128;
    const float4* x1v = (const float4*)g_x1;

    for (int fi = tid; fi < 128*16; fi += 256) {
        int pt = fi >> 4, q = fi & 15;
        float4 v = x1v[(size_t)(i0+pt)*16 + q];
        *(float4*)&sA[pt*KF_LDA + q*4] =
            make_float4(tfbits(v.x), tfbits(v.y), tfbits(v.z), tfbits(v.w));
    }
    if (tid < 128) {
        float s = 0.f;
#pragma unroll
        for (int q = 0; q < 16; q++) {
            float4 v = x1v[(size_t)(i0+tid)*16 + q];
            s += v.x*v.x + v.y*v.y + v.z*v.z + v.w*v.w;
        }
        sqi[tid] = s;
    }

    int spt = tid & 127, ssc = tid >> 7;     // selection: point, scanner half
    float bd[KNN]; int bi[KNN];
    float worst = 3.4e38f; int wslot = 0;
#pragma unroll
    for (int t = 0; t < KNN; t++) { bd[t] = 3.4e38f; bi[t] = 0; }
    float mysq = 0.f;

    for (int jt = 0; jt < 16; jt++) {
        int j0 = b*PP + jt*64;
        __syncthreads();
#pragma unroll
        for (int r = 0; r < 4; r++) {
            int fi = tid + r*256;
            int pt = fi >> 4, q = fi & 15;
            float4 v = x1v[(size_t)(j0+pt)*16 + q];
            *(float4*)&sB[pt*KF_LDA + q*4] =
                make_float4(tfbits(v.x), tfbits(v.y), tfbits(v.z), tfbits(v.w));
        }
        if (tid < 64) {
            float s = 0.f;
#pragma unroll
            for (int q = 0; q < 16; q++) {
                float4 v = x1v[(size_t)(j0+tid)*16 + q];
                s += v.x*v.x + v.y*v.y + v.z*v.z + v.w*v.w;
            }
            sqj[tid] = s;
        }
        __syncthreads();
        // GEMM dot[128 i][64 j], K=64; warp tile 32x32
        float acc[2][4][4];
#pragma unroll
        for (int mi = 0; mi < 2; mi++)
#pragma unroll
            for (int ni = 0; ni < 4; ni++)
#pragma unroll
                for (int c = 0; c < 4; c++) acc[mi][ni][c] = 0.f;
#pragma unroll
        for (int ks = 0; ks < 8; ks++) {
            int k0 = ks*8;
            uint32_t A[2][4];
#pragma unroll
            for (int mi = 0; mi < 2; mi++) {
                int row = wm*32 + mi*16 + g4;
                A[mi][0] = __float_as_uint(sA[row*KF_LDA + k0 + tig]);
                A[mi][1] = __float_as_uint(sA[(row+8)*KF_LDA + k0 + tig]);
                A[mi][2] = __float_as_uint(sA[row*KF_LDA + k0 + tig + 4]);
                A[mi][3] = __float_as_uint(sA[(row+8)*KF_LDA + k0 + tig + 4]);
            }
            uint32_t Bf[4][2];
#pragma unroll
            for (int ni = 0; ni < 4; ni++) {
                int col = wn*32 + ni*8 + g4;
                Bf[ni][0] = __float_as_uint(sB[col*KF_LDA + k0 + tig]);
                Bf[ni][1] = __float_as_uint(sB[col*KF_LDA + k0 + tig + 4]);
            }
#pragma unroll
            for (int mi = 0; mi < 2; mi++)
#pragma unroll
                for (int ni = 0; ni < 4; ni++)
                    mma8(acc[mi][ni][0], acc[mi][ni][1], acc[mi][ni][2], acc[mi][ni][3],
                         A[mi][0], A[mi][1], A[mi][2], A[mi][3], Bf[ni][0], Bf[ni][1]);
        }
#pragma unroll
        for (int mi = 0; mi < 2; mi++) {
#pragma unroll
            for (int ni = 0; ni < 4; ni++) {
                int row = wm*32 + mi*16 + g4, col = wn*32 + ni*8 + tig*2;
                *(float2*)&sdot[row*KF_LDA + col]     = make_float2(acc[mi][ni][0], acc[mi][ni][1]);
                *(float2*)&sdot[(row+8)*KF_LDA + col] = make_float2(acc[mi][ni][2], acc[mi][ni][3]);
            }
        }
        __syncthreads();
        // split selection: scanner ssc covers j-cols [ssc*32, ssc*32+32)
        {
            if (jt == 0) mysq = sqi[spt];
            const float4* drow4 = (const float4*)(sdot + spt*KF_LDA) + ssc*8;
            const float4* sqj4  = (const float4*)sqj + ssc*8;
            int jbase = jt*64 + ssc*32;
#pragma unroll 4
            for (int j4 = 0; j4 < 8; j4++) {
                float4 dv = drow4[j4];
                float4 sv = sqj4[j4];
                float d0 = mysq + sv.x - 2.0f*dv.x;
                float d1 = mysq + sv.y - 2.0f*dv.y;
                float d2 = mysq + sv.z - 2.0f*dv.z;
                float d3 = mysq + sv.w - 2.0f*dv.w;
                float mn = fminf(fminf(d0, d1), fminf(d2, d3));
                if (mn < worst) {
                    tk_ins(bd, bi, worst, wslot, d0, jbase + 4*j4 + 0);
                    tk_ins(bd, bi, worst, wslot, d1, jbase + 4*j4 + 1);
                    tk_ins(bd, bi, worst, wslot, d2, jbase + 4*j4 + 2);
                    tk_ins(bd, bi, worst, wslot, d3, jbase + 4*j4 + 3);
                }
            }
        }
    }
    __syncthreads();
    if (ssc == 1) {
#pragma unroll
        for (int t = 0; t < KNN; t++) { sbd[spt*KNN + t] = bd[t]; sbi[spt*KNN + t] = bi[t]; }
    }
    __syncthreads();
    if (ssc == 0) {
#pragma unroll
        for (int t = 0; t < KNN; t++)
            tk_ins(bd, bi, worst, wslot, sbd[spt*KNN + t], sbi[spt*KNN + t]);
        int gi = i0 + spt;
#pragma unroll
        for (int t = 0; t < KNN; t++) g_idx[(size_t)gi*KNN + t] = b*PP + bi[t];
    }
}

// ---------------- EdgeConv2 v6: persistent grid-stride + flat build + coop base + diff GEMM ----------------
#define C2_LDD 68
#define C2_LDW 136
#define C2_LDB 132
__global__ __launch_bounds__(256, 2) void conv2_kernel(
    const float* __restrict__ w, const float* __restrict__ bias)
{
    extern __shared__ float sm[];
    float* sWb   = sm;                        // 64*136
    float* sD    = sm + 64*C2_LDW;            // 160*68
    float* sXi   = sD + 160*C2_LDD;           // 8*68
    float* sBase = sXi + 8*68;                // 8*132
    float* sbias = sBase + 8*C2_LDB;          // 128
    int*   sJ    = (int*)(sbias + 128);       // 160
    int*   sP    = sJ + 160;                  // 160

    int tid = threadIdx.x, lane = tid & 31, warp = tid >> 5;
    int g4 = lane >> 2, tig = lane & 3;
    int wm = warp >> 2, wn = warp & 3;
    int mB = wm*80, nB = wn*32;

    for (int fi = tid; fi < 2048; fi += 256) {
        int kk = fi >> 5, nq = fi & 31;
        float4 v = ((const float4*)w)[(64+kk)*32 + nq];
        *(float4*)&sWb[kk*C2_LDW + nq*4] =
            make_float4(tfbits(v.x), tfbits(v.y), tfbits(v.z), tfbits(v.w));
    }
    if (tid < 128) sbias[tid] = bias[tid];

    const float4* x1v = (const float4*)g_x1;

    for (int g = blockIdx.x; g < 4096; g += gridDim.x) {
        int ibase = g * 8;
        __syncthreads();
        if (tid < 128) {
            int p = tid >> 4, q = tid & 15;
            *(float4*)&sXi[p*68 + q*4] = x1v[(size_t)(ibase+p)*16 + q];
        }
        if (tid < 160) {
            int p = tid / 20;
            sJ[tid] = g_idx[(size_t)(ibase+p)*KNN + (tid - p*20)];
            sP[tid] = p;
        }
        __syncthreads();
#pragma unroll
        for (int it = 0; it < 10; it++) {
            int fi = tid + it*256;
            int row = fi >> 4, q = fi & 15;
            int j = sJ[row], p = sP[row];
            float4 xj = x1v[(size_t)j*16 + q];
            float4 xi = *(const float4*)&sXi[p*68 + q*4];
            *(float4*)&sD[row*C2_LDD + q*4] =
                make_float4(tfbits(xj.x-xi.x), tfbits(xj.y-xi.y),
                            tfbits(xj.z-xi.z), tfbits(xj.w-xi.w));
        }
        {
            int p = lane >> 2, c4 = lane & 3;
            int colq = warp*4 + c4;
            const float* xir = &sXi[p*68];
            float4 acc4 = ((const float4*)sbias)[colq];
#pragma unroll 8
            for (int k = 0; k < 64; k++) {
                float xv = xir[k];
                float4 wv = ((const float4*)w)[k*32 + colq];
                acc4.x = fmaf(xv, wv.x, acc4.x); acc4.y = fmaf(xv, wv.y, acc4.y);
                acc4.z = fmaf(xv, wv.z, acc4.z); acc4.w = fmaf(xv, wv.w, acc4.w);
            }
            *(float4*)&sBase[p*C2_LDB + colq*4] = acc4;
        }
        __syncthreads();
        float acc[5][4][4];
#pragma unroll
        for (int mi = 0; mi < 5; mi++)
#pragma unroll
            for (int ni = 0; ni < 4; ni++)
#pragma unroll
                for (int c = 0; c < 4; c++) acc[mi][ni][c] = 0.f;
#pragma unroll 1
        for (int ks = 0; ks < 8; ks++) {
            int k0 = ks*8;
            uint32_t A[5][4];
#pragma unroll
            for (int mi = 0; mi < 5; mi++) {
                int row = mB + mi*16 + g4;
                A[mi][0] = __float_as_uint(sD[row*C2_LDD + k0 + tig]);
                A[mi][1] = __float_as_uint(sD[(row+8)*C2_LDD + k0 + tig]);
                A[mi][2] = __float_as_uint(sD[row*C2_LDD + k0 + tig + 4]);
                A[mi][3] = __float_as_uint(sD[(row+8)*C2_LDD + k0 + tig + 4]);
            }
            uint32_t Bf[4][2];
#pragma unroll
            for (int ni = 0; ni < 4; ni++) {
                int col = nB + ni*8 + g4;
                Bf[ni][0] = __float_as_uint(sWb[(k0+tig)*C2_LDW + col]);
                Bf[ni][1] = __float_as_uint(sWb[(k0+tig+4)*C2_LDW + col]);
            }
#pragma unroll
            for (int mi = 0; mi < 5; mi++)
#pragma unroll
                for (int ni = 0; ni < 4; ni++)
                    mma8(acc[mi][ni][0], acc[mi][ni][1], acc[mi][ni][2], acc[mi][ni][3],
                         A[mi][0], A[mi][1], A[mi][2], A[mi][3], Bf[ni][0], Bf[ni][1]);
        }
        float pm[4][4][2];
#pragma unroll
        for (int p = 0; p < 4; p++)
#pragma unroll
            for (int ni = 0; ni < 4; ni++) { pm[p][ni][0] = -3.4e38f; pm[p][ni][1] = -3.4e38f; }
        bool hi = (g4 >= 4);
#pragma unroll
        for (int ni = 0; ni < 4; ni++) {
            pm[0][ni][0] = fmaxf(pm[0][ni][0], acc[0][ni][0]);
            pm[0][ni][1] = fmaxf(pm[0][ni][1], acc[0][ni][1]);
            if (!hi) { pm[0][ni][0] = fmaxf(pm[0][ni][0], acc[1][ni][0]);
                       pm[0][ni][1] = fmaxf(pm[0][ni][1], acc[1][ni][1]); }
            else     { pm[1][ni][0] = fmaxf(pm[1][ni][0], acc[1][ni][0]);
                       pm[1][ni][1] = fmaxf(pm[1][ni][1], acc[1][ni][1]); }
            pm[1][ni][0] = fmaxf(pm[1][ni][0], acc[2][ni][0]);
            pm[1][ni][1] = fmaxf(pm[1][ni][1], acc[2][ni][1]);
            pm[2][ni][0] = fmaxf(pm[2][ni][0], acc[3][ni][0]);
            pm[2][ni][1] = fmaxf(pm[2][ni][1], acc[3][ni][1]);
            pm[3][ni][0] = fmaxf(pm[3][ni][0], acc[4][ni][0]);
            pm[3][ni][1] = fmaxf(pm[3][ni][1], acc[4][ni][1]);
            pm[0][ni][0] = fmaxf(pm[0][ni][0], acc[0][ni][2]);
            pm[0][ni][1] = fmaxf(pm[0][ni][1], acc[0][ni][3]);
            pm[1][ni][0] = fmaxf(pm[1][ni][0], acc[1][ni][2]);
            pm[1][ni][1] = fmaxf(pm[1][ni][1], acc[1][ni][3]);
            pm[2][ni][0] = fmaxf(pm[2][ni][0], acc[2][ni][2]);
            pm[2][ni][1] = fmaxf(pm[2][ni][1], acc[2][ni][3]);
            if (!hi) { pm[2][ni][0] = fmaxf(pm[2][ni][0], acc[3][ni][2]);
                       pm[2][ni][1] = fmaxf(pm[2][ni][1], acc[3][ni][3]); }
            else     { pm[3][ni][0] = fmaxf(pm[3][ni][0], acc[3][ni][2]);
                       pm[3][ni][1] = fmaxf(pm[3][ni][1], acc[3][ni][3]); }
            pm[3][ni][0] = fmaxf(pm[3][ni][0], acc[4][ni][2]);
            pm[3][ni][1] = fmaxf(pm[3][ni][1], acc[4][ni][3]);
        }
#pragma unroll
        for (int off = 4; off < 32; off <<= 1)
#pragma unroll
            for (int p = 0; p < 4; p++)
#pragma unroll
                for (int ni = 0; ni < 4; ni++) {
                    pm[p][ni][0] = fmaxf(pm[p][ni][0], __shfl_xor_sync(0xffffffff, pm[p][ni][0], off));
                    pm[p][ni][1] = fmaxf(pm[p][ni][1], __shfl_xor_sync(0xffffffff, pm[p][ni][1], off));
                }
        if (g4 == 0) {
#pragma unroll
            for (int p = 0; p < 4; p++) {
                int wp = wm*4 + p;
#pragma unroll
                for (int ni = 0; ni < 4; ni++) {
                    int col = nB + ni*8 + tig*2;
                    float b0v = sBase[wp*C2_LDB + col];
                    float b1v = sBase[wp*C2_LDB + col + 1];
                    float2 o;
                    o.x = fmaxf(pm[p][ni][0] + b0v, 0.f);
                    o.y = fmaxf(pm[p][ni][1] + b1v, 0.f);
                    *(float2*)&g_x2[(size_t)(ibase+wp)*128 + col] = o;
                }
            }
        }
    }
}

// ---------------- l1 (192->1024) tf32 GEMM, k-chunk 32, + fused relu + P-max ----------------
#define L1_LDA 36
__global__ __launch_bounds__(256) void l1max_kernel(
    const float* __restrict__ w, const float* __restrict__ bias)
{
    __shared__ float sA[128*L1_LDA];
    __shared__ float sB[32*136];
    __shared__ float sbias[128];
    __shared__ unsigned int sred[128];
    int tid = threadIdx.x;
    int lane = tid & 31, warp = tid >> 5;
    int g4 = lane >> 2, tig = lane & 3;
    int b = blockIdx.z;
    int n0 = blockIdx.x * 128, m0 = blockIdx.y * 128;
    int pbase = b * PP + m0;
    const float4* x1v = (const float4*)g_x1;
    const float4* x2v = (const float4*)g_x2;
    const float4* wv  = (const float4*)w;
    if (tid < 128) { sred[tid] = 0u; sbias[tid] = bias[n0 + tid]; }

    int wm = warp >> 2, wn = warp & 3;
    float acc[4][4][4];
#pragma unroll
    for (int mi = 0; mi < 4; mi++)
#pragma unroll
        for (int ni = 0; ni < 4; ni++)
#pragma unroll
            for (int c = 0; c < 4; c++) acc[mi][ni][c] = 0.f;

    for (int ks = 0; ks < 6; ks++) {
        __syncthreads();
#pragma unroll
        for (int r = 0; r < 4; r++) {
            int fi = tid + r*256;
            int pt = fi >> 3, kq = fi & 7;
            float4 v = (ks < 2) ? x1v[(size_t)(pbase+pt)*16 + ks*8 + kq]
                                : x2v[(size_t)(pbase+pt)*32 + (ks-2)*8 + kq];
            *(float4*)&sA[pt*L1_LDA + kq*4] =
                make_float4(tfbits(v.x), tfbits(v.y), tfbits(v.z), tfbits(v.w));
        }
#pragma unroll
        for (int r = 0; r < 4; r++) {
            int fi = tid + r*256;
            int kk = fi >> 5, nq = fi & 31;
            float4 v = wv[(size_t)(ks*32+kk)*256 + (n0>>2) + nq];
            *(float4*)&sB[kk*136 + nq*4] =
                make_float4(tfbits(v.x), tfbits(v.y), tfbits(v.z), tfbits(v.w));
        }
        __syncthreads();
#pragma unroll
        for (int kh = 0; kh < 4; kh++) {
            int k0 = kh*8;
            uint32_t A[4][4];
#pragma unroll
            for (int mi = 0; mi < 4; mi++) {
                int row = wm*64 + mi*16 + g4;
                A[mi][0] = __float_as_uint(sA[row*L1_LDA + k0 + tig]);
                A[mi][1] = __float_as_uint(sA[(row+8)*L1_LDA + k0 + tig]);
                A[mi][2] = __float_as_uint(sA[row*L1_LDA + k0 + tig + 4]);
                A[mi][3] = __float_as_uint(sA[(row+8)*L1_LDA + k0 + tig + 4]);
            }
            uint32_t Bf[4][2];
#pragma unroll
            for (int ni = 0; ni < 4; ni++) {
                int col = wn*32 + ni*8 + g4;
                Bf[ni][0] = __float_as_uint(sB[(k0+tig)*136 + col]);
                Bf[ni][1] = __float_as_uint(sB[(k0+tig+4)*136 + col]);
            }
#pragma unroll
            for (int mi = 0; mi < 4; mi++)
#pragma unroll
                for (int ni = 0; ni < 4; ni++)
                    mma8(acc[mi][ni][0], acc[mi][ni][1], acc[mi][ni][2], acc[mi][ni][3],
                         A[mi][0], A[mi][1], A[mi][2], A[mi][3], Bf[ni][0], Bf[ni][1]);
        }
    }
#pragma unroll
    for (int ni = 0; ni < 4; ni++) {
        float v0 = -3.4e38f, v1 = -3.4e38f;
#pragma unroll
        for (int mi = 0; mi < 4; mi++) {
            v0 = fmaxf(v0, fmaxf(acc[mi][ni][0], acc[mi][ni][2]));
            v1 = fmaxf(v1, fmaxf(acc[mi][ni][1], acc[mi][ni][3]));
        }
#pragma unroll
        for (int off = 4; off < 32; off <<= 1) {
            v0 = fmaxf(v0, __shfl_xor_sync(0xffffffff, v0, off));
            v1 = fmaxf(v1, __shfl_xor_sync(0xffffffff, v1, off));
        }
        if (g4 == 0) {
            int col = wn*32 + ni*8 + tig*2;
            float a0 = fmaxf(v0 + sbias[col], 0.f);
            float a1 = fmaxf(v1 + sbias[col+1], 0.f);
            atomicMax(&sred[col],   __float_as_uint(a0));
            atomicMax(&sred[col+1], __float_as_uint(a1));
        }
    }
    __syncthreads();
    if (tid < 128) atomicMax(&g_pool[b*1024 + n0 + tid], sred[tid]);
}

// ---------------- head0: h0 = relu(pool @ m_w0 + b0), grid (2, 32) ----------------
__global__ __launch_bounds__(256) void head0_kernel(
    const float* __restrict__ w0, const float* __restrict__ b0)
{
    __shared__ float sp[1024];
    int b = blockIdx.y, tid = threadIdx.x;
    int o = blockIdx.x * 256 + tid;
    for (int c = tid; c < 1024; c += 256) sp[c] = __uint_as_float(g_pool[b*1024 + c]);
    __syncthreads();
    float a0 = 0.f, a1 = 0.f, a2 = 0.f, a3 = 0.f;
    for (int c = 0; c < 1024; c += 4) {
        a0 = fmaf(sp[c+0], w0[(size_t)(c+0)*512 + o], a0);
        a1 = fmaf(sp[c+1], w0[(size_t)(c+1)*512 + o], a1);
        a2 = fmaf(sp[c+2], w0[(size_t)(c+2)*512 + o], a2);
        a3 = fmaf(sp[c+3], w0[(size_t)(c+3)*512 + o], a3);
    }
    g_h0[b*512 + o] = fmaxf(((a0 + a1) + (a2 + a3)) + b0[o], 0.f);
}

// ---------------- head1: 512->256 relu ->40 + log_softmax, grid 32 ----------------
__global__ __launch_bounds__(256) void head1_kernel(
    const float* __restrict__ w1, const float* __restrict__ b1,
    const float* __restrict__ w2, const float* __restrict__ b2,
    float* __restrict__ out)
{
    __shared__ float sh0[512], sh1[256], sl[40], red[2];
    int b = blockIdx.x, tid = threadIdx.x;
    for (int c = tid; c < 512; c += 256) sh0[c] = g_h0[b*512 + c];
    __syncthreads();
    {
        float a0 = 0.f, a1 = 0.f;
        for (int c = 0; c < 512; c += 2) {
            a0 = fmaf(sh0[c],   w1[(size_t)c*256 + tid],     a0);
            a1 = fmaf(sh0[c+1], w1[(size_t)(c+1)*256 + tid], a1);
        }
        sh1[tid] = fmaxf(a0 + a1 + b1[tid], 0.f);
    }
    __syncthreads();
    if (tid < 40) {
        float a = b2[tid];
        for (int c = 0; c < 256; c++) a += sh1[c] * w2[c*40 + tid];
        sl[tid] = a;
    }
    __syncthreads();
    if (tid == 0) {
        float mxv = -3.4e38f;
        for (int t = 0; t < 40; t++) mxv = fmaxf(mxv, sl[t]);
        float s = 0.f;
        for (int t = 0; t < 40; t++) s += expf(sl[t] - mxv);
        red[0] = mxv; red[1] = logf(s);
    }
    __syncthreads();
    if (tid < 40) out[b*40 + tid] = sl[tid] - red[0] - red[1];
}

// ---------------- launch ----------------
extern "C" void kernel_launch(void* const* d_in, const int* in_sizes, int n_in,
                              void* d_out, int out_size)
{
    const float* pos   = (const float*)d_in[0];
    const float* c1_w0 = (const float*)d_in[2];
    const float* c1_b0 = (const float*)d_in[3];
    const float* c1_w1 = (const float*)d_in[4];
    const float* c1_b1 = (const float*)d_in[5];
    const float* c1_w2 = (const float*)d_in[6];
    const float* c1_b2 = (const float*)d_in[7];
    const float* c2_w0 = (const float*)d_in[8];
    const float* c2_b0 = (const float*)d_in[9];
    const float* l1_w  = (const float*)d_in[10];
    const float* l1_b  = (const float*)d_in[11];
    const float* m_w0  = (const float*)d_in[12];
    const float* m_b0  = (const float*)d_in[13];
    const float* m_w1  = (const float*)d_in[14];
    const float* m_b1  = (const float*)d_in[15];
    const float* m_w2  = (const float*)d_in[16];
    const float* m_b2  = (const float*)d_in[17];
    float* out = (float*)d_out;

    const int smem_kpos  = 4096*4 + 5120*4 + 5120*4;                                     // 57344
    const int smem_conv1 = (576 + 4608 + 128 + 160*C1_LDD) * 4;                          // 64768
    const int smem_knn2  = (128*KF_LDA + 64*KF_LDA + 128*KF_LDA + 128 + 64
                            + 128*KNN + 128*KNN) * 4;                                     // 108288
    const int smem_conv2 = (64*C2_LDW + 160*C2_LDD + 8*68 + 8*C2_LDB + 128 + 320) * 4;   // ~86.5 KB

    cudaFuncSetAttribute(knn_pos_kernel,  cudaFuncAttributeMaxDynamicSharedMemorySize, smem_kpos);
    cudaFuncSetAttribute(conv1_kernel,    cudaFuncAttributeMaxDynamicSharedMemorySize, smem_conv1);
    cudaFuncSetAttribute(knn_feat_kernel, cudaFuncAttributeMaxDynamicSharedMemorySize, smem_knn2);
    cudaFuncSetAttribute(conv2_kernel,    cudaFuncAttributeMaxDynamicSharedMemorySize, smem_conv2);

    fuse_w01_kernel<<<1, 512>>>(c1_w0, c1_b0, c1_w1, c1_b1);
    knn_pos_kernel<<<dim3(4, 32), 512, smem_kpos>>>(pos);
    conv1_kernel<<<296, 256, smem_conv1>>>(pos, c1_w2, c1_b2);
    knn_feat_kernel<<<dim3(8, 32), 256, smem_knn2>>>();
    conv2_kernel<<<296, 256, smem_conv2>>>(c2_w0, c2_b0);
    l1max_kernel<<<dim3(8, 8, 32), 256>>>(l1_w, l1_b);
    head0_kernel<<<dim3(2, 32), 256>>>(m_w0, m_b0);
    head1_kernel<<<32, 256>>>(m_w1, m_b1, m_w2, m_b2, out);
}

// round 15
// speedup vs baseline: 11.2543x; 1.0596x over previous
#include <cuda_runtime.h>
#include <math.h>
#include <stdint.h>

#define BB 32
#define PP 1024
#define KNN 20
#define NPTS (BB*PP)

// ---------------- scratch (device globals; no allocs allowed) ----------------
__device__ __align__(16) float g_x1[NPTS*64];
__device__ __align__(16) float g_x2[NPTS*128];
__device__ int g_idx[NPTS*KNN];
__device__ unsigned int g_pool[BB*1024];
__device__ __align__(16) float g_h0[BB*512];
__device__ __align__(16) float g_w01[8*64];
__device__ __align__(16) float g_b01[64];

// ---------------- tf32 mma helpers ----------------
__device__ __forceinline__ uint32_t f2tf(float x) {
    uint32_t r; asm("cvt.rna.tf32.f32 %0, %1;" : "=r"(r) : "f"(x)); return r;
}
__device__ __forceinline__ float tfbits(float x) {
    return __uint_as_float(f2tf(x));
}
__device__ __forceinline__ void mma8(float& c0, float& c1, float& c2, float& c3,
                                     uint32_t a0, uint32_t a1, uint32_t a2, uint32_t a3,
                                     uint32_t b0, uint32_t b1)
{
    asm volatile("mma.sync.aligned.m16n8k8.row.col.f32.tf32.tf32.f32 "
                 "{%0,%1,%2,%3},{%4,%5,%6,%7},{%8,%9},{%0,%1,%2,%3};"
                 : "+f"(c0), "+f"(c1), "+f"(c2), "+f"(c3)
                 : "r"(a0), "r"(a1), "r"(a2), "r"(a3), "r"(b0), "r"(b1));
}

// top-k insertion (strict <, keeps earliest index on ties — matches jax top_k).
// FULL unrolled bubble with static indices only — proven spill-free (R12).
__device__ __forceinline__ void topk_insert(float* bd, int* bi, float d, int j)
{
    if (d < bd[KNN-1]) {
        bd[KNN-1] = d; bi[KNN-1] = j;
#pragma unroll
        for (int t = KNN-1; t > 0; t--) {
            if (bd[t] < bd[t-1]) {
                float td = bd[t]; bd[t] = bd[t-1]; bd[t-1] = td;
                int ti = bi[t]; bi[t] = bi[t-1]; bi[t-1] = ti;
            }
        }
    }
}

// 5 m-tiles x 2 n-tiles warp GEMM (used by conv1)
__device__ __forceinline__ void mma_5x2(
    const float* sD, const float* sW, float acc[5][2][4],
    int mB, int nB, int g4, int tig, int ksteps, int ldd, int ldw)
{
#pragma unroll
    for (int mi = 0; mi < 5; mi++)
#pragma unroll
        for (int ni = 0; ni < 2; ni++)
#pragma unroll
            for (int c = 0; c < 4; c++) acc[mi][ni][c] = 0.f;
#pragma unroll 1
    for (int ks = 0; ks < ksteps; ks++) {
        int k0 = ks * 8;
        uint32_t A[5][4];
#pragma unroll
        for (int mi = 0; mi < 5; mi++) {
            int row = mB + mi*16 + g4;
            A[mi][0] = __float_as_uint(sD[row*ldd + k0 + tig]);
            A[mi][1] = __float_as_uint(sD[(row+8)*ldd + k0 + tig]);
            A[mi][2] = __float_as_uint(sD[row*ldd + k0 + tig + 4]);
            A[mi][3] = __float_as_uint(sD[(row+8)*ldd + k0 + tig + 4]);
        }
        uint32_t Bf[2][2];
#pragma unroll
        for (int ni = 0; ni < 2; ni++) {
            int col = nB + ni*8 + g4;
            Bf[ni][0] = __float_as_uint(sW[(k0+tig)*ldw + col]);
            Bf[ni][1] = __float_as_uint(sW[(k0+tig+4)*ldw + col]);
        }
#pragma unroll
        for (int mi = 0; mi < 5; mi++)
#pragma unroll
            for (int ni = 0; ni < 2; ni++)
                mma8(acc[mi][ni][0], acc[mi][ni][1], acc[mi][ni][2], acc[mi][ni][3],
                     A[mi][0], A[mi][1], A[mi][2], A[mi][3], Bf[ni][0], Bf[ni][1]);
    }
}

__device__ __forceinline__ void wb_5x2(
    float* sD, float acc[5][2][4], const float* bias,
    int mB, int nB, int g4, int tig, int ldd, int mode)
{
#pragma unroll
    for (int mi = 0; mi < 5; mi++) {
#pragma unroll
        for (int ni = 0; ni < 2; ni++) {
            int row = mB + mi*16 + g4, col = nB + ni*8 + tig*2;
            float v0 = acc[mi][ni][0], v1 = acc[mi][ni][1];
            float v2 = acc[mi][ni][2], v3 = acc[mi][ni][3];
            float ba = bias[col], bb = bias[col+1];
            v0 += ba; v1 += bb; v2 += ba; v3 += bb;
            if (mode == 1) {
                v0 = fmaxf(v0, 0.f); v1 = fmaxf(v1, 0.f);
                v2 = fmaxf(v2, 0.f); v3 = fmaxf(v3, 0.f);
            }
            v0 = tfbits(v0); v1 = tfbits(v1); v2 = tfbits(v2); v3 = tfbits(v3);
            sD[row*ldd + col] = v0;     sD[row*ldd + col + 1] = v1;
            sD[(row+8)*ldd + col] = v2; sD[(row+8)*ldd + col + 1] = v3;
        }
    }
}

// ---------------- prologue: W01 = W0 @ W1, b01 = b0 @ W1 + b1 (exact fp32) ----------------
__global__ __launch_bounds__(512) void fuse_w01_kernel(
    const float* __restrict__ w0, const float* __restrict__ b0,
    const float* __restrict__ w1, const float* __restrict__ b1)
{
    int tid = threadIdx.x;
    if (tid < 384) {
        int c = tid >> 6, o = tid & 63;
        float s = 0.f;
        for (int h = 0; h < 64; h++) s = fmaf(w0[c*64 + h], w1[h*64 + o], s);
        g_w01[c*64 + o] = s;
    } else if (tid < 448) {
        int o = tid - 384;
        float s = b1[o];
        for (int h = 0; h < 64; h++) s = fmaf(b0[h], w1[h*64 + o], s);
        g_b01[o] = s;
    }
}

// ---------------- KNN over 3-D positions: split-scan + 8-wide gate + pool zero ----------------
__global__ __launch_bounds__(512) void knn_pos_kernel(const float* __restrict__ pos)
{
    extern __shared__ float smk[];
    float4* spos = (float4*)smk;                     // 1024 float4
    float*  sbd  = smk + 4096;                       // 256*20
    int*    sbi  = (int*)(smk + 4096 + 5120);        // 256*20
    int tid = threadIdx.x;
    int lb = blockIdx.y*4 + blockIdx.x;
    if (tid < 256) g_pool[lb*256 + tid] = 0u;
    int b = blockIdx.y;
    const float* p = pos + (size_t)b * PP * 3;
    for (int j = tid; j < PP; j += 512) {
        float x = p[3*j], y = p[3*j+1], z = p[3*j+2];
        spos[j] = make_float4(x, y, z, x*x + y*y + z*z);
    }
    __syncthreads();
    int pt = tid & 255, s = tid >> 8;
    int il = blockIdx.x * 256 + pt;
    float4 me = spos[il];
    float xi = me.x, yi = me.y, zi = me.z, sqi = me.w;
    float bd[KNN]; int bi[KNN];
#pragma unroll
    for (int t = 0; t < KNN; t++) { bd[t] = 3.4e38f; bi[t] = 0; }
    int j8base = s * 64;
    for (int j8 = j8base; j8 < j8base + 64; j8++) {
        float4 v0 = spos[8*j8+0], v1 = spos[8*j8+1], v2 = spos[8*j8+2], v3 = spos[8*j8+3];
        float4 v4 = spos[8*j8+4], v5 = spos[8*j8+5], v6 = spos[8*j8+6], v7 = spos[8*j8+7];
        float d0 = sqi + v0.w - 2.0f*(xi*v0.x + yi*v0.y + zi*v0.z);
        float d1 = sqi + v1.w - 2.0f*(xi*v1.x + yi*v1.y + zi*v1.z);
        float d2 = sqi + v2.w - 2.0f*(xi*v2.x + yi*v2.y + zi*v2.z);
        float d3 = sqi + v3.w - 2.0f*(xi*v3.x + yi*v3.y + zi*v3.z);
        float d4 = sqi + v4.w - 2.0f*(xi*v4.x + yi*v4.y + zi*v4.z);
        float d5 = sqi + v5.w - 2.0f*(xi*v5.x + yi*v5.y + zi*v5.z);
        float d6 = sqi + v6.w - 2.0f*(xi*v6.x + yi*v6.y + zi*v6.z);
        float d7 = sqi + v7.w - 2.0f*(xi*v7.x + yi*v7.y + zi*v7.z);
        float mn = fminf(fminf(fminf(d0, d1), fminf(d2, d3)),
                         fminf(fminf(d4, d5), fminf(d6, d7)));
        if (mn < bd[KNN-1]) {
            topk_insert(bd, bi, d0, 8*j8+0);
            topk_insert(bd, bi, d1, 8*j8+1);
            topk_insert(bd, bi, d2, 8*j8+2);
            topk_insert(bd, bi, d3, 8*j8+3);
            topk_insert(bd, bi, d4, 8*j8+4);
            topk_insert(bd, bi, d5, 8*j8+5);
            topk_insert(bd, bi, d6, 8*j8+6);
            topk_insert(bd, bi, d7, 8*j8+7);
        }
    }
    if (s == 1) {
#pragma unroll
        for (int t = 0; t < KNN; t++) { sbd[pt*KNN + t] = bd[t]; sbi[pt*KNN + t] = bi[t]; }
    }
    __syncthreads();
    if (s == 0) {
        for (int t = 0; t < KNN; t++) {
            float d = sbd[pt*KNN + t];
            if (!(d < bd[KNN-1])) break;
            topk_insert(bd, bi, d, sbi[pt*KNN + t]);
        }
        int gi = b * PP + il;
#pragma unroll
        for (int t = 0; t < KNN; t++) g_idx[gi*KNN + t] = b * PP + bi[t];
    }
}

// ---------------- EdgeConv1 v2: fused W01, persistent ----------------
#define C1_LDD 68
#define C1_LDW 72
__global__ __launch_bounds__(256, 2) void conv1_kernel(
    const float* __restrict__ pos,
    const float* __restrict__ w2, const float* __restrict__ b2)
{
    extern __shared__ float sm[];
    float* sW01 = sm;             // 8*72
    float* sW2  = sm + 576;       // 64*72
    float* sb01 = sm + 5184;      // 64
    float* sb2  = sm + 5248;      // 64
    float* sD   = sm + 5312;      // 160*68

    int tid = threadIdx.x, lane = tid & 31, warp = tid >> 5;
    int g4 = lane >> 2, tig = lane & 3;
    int wm = warp >> 2, wn = warp & 3;
    int mB = wm * 80, nB = wn * 16;

    for (int fi = tid; fi < 512; fi += 256) {
        int kk = fi >> 6, o = fi & 63;
        sW01[kk*C1_LDW + o] = (kk < 6) ? tfbits(g_w01[kk*64 + o]) : 0.f;
    }
    for (int fi = tid; fi < 4096; fi += 256) {
        int kk = fi >> 6, o = fi & 63;
        sW2[kk*C1_LDW + o] = tfbits(w2[fi]);
    }
    if (tid < 64) { sb01[tid] = g_b01[tid]; sb2[tid] = b2[tid]; }

    float acc[5][2][4];
    for (int g = blockIdx.x; g < 4096; g += gridDim.x) {
        int ibase = g * 8;
        __syncthreads();
        if (tid < 160) {
            int p = tid / 20, e = tid - p*20;
            int i = ibase + p;
            int j = g_idx[i*KNN + e];
            float xx = pos[i*3], xy = pos[i*3+1], xz = pos[i*3+2];
            float jx = pos[j*3], jy = pos[j*3+1], jz = pos[j*3+2];
            float* dr = sD + tid*C1_LDD;
            dr[0] = tfbits(xx); dr[1] = tfbits(xy); dr[2] = tfbits(xz);
            dr[3] = tfbits(jx-xx); dr[4] = tfbits(jy-xy); dr[5] = tfbits(jz-xz);
            dr[6] = 0.f; dr[7] = 0.f;
        }
        __syncthreads();
        mma_5x2(sD, sW01, acc, mB, nB, g4, tig, 1, C1_LDD, C1_LDW);
        __syncthreads();
        wb_5x2(sD, acc, sb01, mB, nB, g4, tig, C1_LDD, 1);
        __syncthreads();
        mma_5x2(sD, sW2, acc, mB, nB, g4, tig, 8, C1_LDD, C1_LDW);
        {
            float pm[4][2][2];
#pragma unroll
            for (int p = 0; p < 4; p++)
#pragma unroll
                for (int ni = 0; ni < 2; ni++) { pm[p][ni][0] = -3.4e38f; pm[p][ni][1] = -3.4e38f; }
            bool hi = (g4 >= 4);
#pragma unroll
            for (int ni = 0; ni < 2; ni++) {
                pm[0][ni][0] = fmaxf(pm[0][ni][0], acc[0][ni][0]);
                pm[0][ni][1] = fmaxf(pm[0][ni][1], acc[0][ni][1]);
                if (!hi) { pm[0][ni][0] = fmaxf(pm[0][ni][0], acc[1][ni][0]);
                           pm[0][ni][1] = fmaxf(pm[0][ni][1], acc[1][ni][1]); }
                else     { pm[1][ni][0] = fmaxf(pm[1][ni][0], acc[1][ni][0]);
                           pm[1][ni][1] = fmaxf(pm[1][ni][1], acc[1][ni][1]); }
                pm[1][ni][0] = fmaxf(pm[1][ni][0], acc[2][ni][0]);
                pm[1][ni][1] = fmaxf(pm[1][ni][1], acc[2][ni][1]);
                pm[2][ni][0] = fmaxf(pm[2][ni][0], acc[3][ni][0]);
                pm[2][ni][1] = fmaxf(pm[2][ni][1], acc[3][ni][1]);
                pm[3][ni][0] = fmaxf(pm[3][ni][0], acc[4][ni][0]);
                pm[3][ni][1] = fmaxf(pm[3][ni][1], acc[4][ni][1]);
                pm[0][ni][0] = fmaxf(pm[0][ni][0], acc[0][ni][2]);
                pm[0][ni][1] = fmaxf(pm[0][ni][1], acc[0][ni][3]);
                pm[1][ni][0] = fmaxf(pm[1][ni][0], acc[1][ni][2]);
                pm[1][ni][1] = fmaxf(pm[1][ni][1], acc[1][ni][3]);
                pm[2][ni][0] = fmaxf(pm[2][ni][0], acc[2][ni][2]);
                pm[2][ni][1] = fmaxf(pm[2][ni][1], acc[2][ni][3]);
                if (!hi) { pm[2][ni][0] = fmaxf(pm[2][ni][0], acc[3][ni][2]);
                           pm[2][ni][1] = fmaxf(pm[2][ni][1], acc[3][ni][3]); }
                else     { pm[3][ni][0] = fmaxf(pm[3][ni][0], acc[3][ni][2]);
                           pm[3][ni][1] = fmaxf(pm[3][ni][1], acc[3][ni][3]); }
                pm[3][ni][0] = fmaxf(pm[3][ni][0], acc[4][ni][2]);
                pm[3][ni][1] = fmaxf(pm[3][ni][1], acc[4][ni][3]);
            }
#pragma unroll
            for (int off = 4; off < 32; off <<= 1)
#pragma unroll
                for (int p = 0; p < 4; p++)
#pragma unroll
                    for (int ni = 0; ni < 2; ni++) {
                        pm[p][ni][0] = fmaxf(pm[p][ni][0], __shfl_xor_sync(0xffffffff, pm[p][ni][0], off));
                        pm[p][ni][1] = fmaxf(pm[p][ni][1], __shfl_xor_sync(0xffffffff, pm[p][ni][1], off));
                    }
            if (g4 == 0) {
#pragma unroll
                for (int p = 0; p < 4; p++) {
                    int wp = wm*4 + p;
#pragma unroll
                    for (int ni = 0; ni < 2; ni++) {
                        int col = nB + ni*8 + tig*2;
                        float2 o;
                        o.x = fmaxf(pm[p][ni][0] + sb2[col],   0.f);
                        o.y = fmaxf(pm[p][ni][1] + sb2[col+1], 0.f);
                        *(float2*)&g_x1[(size_t)(ibase+wp)*64 + col] = o;
                    }
                }
            }
        }
    }
}

// ---------------- KNN over 64-D features v4: split-scan + 8-wide gate ----------------
#define KF_LDA 68
__global__ __launch_bounds__(256, 2) void knn_feat_kernel()
{
    extern __shared__ float sm[];
    float* sA   = sm;                        // 128*68  (Xi tf32)
    float* sB   = sA + 128*KF_LDA;           // 64*68   (Xj tf32)
    float* sdot = sB + 64*KF_LDA;            // 128*68
    float* sqi  = sdot + 128*KF_LDA;         // 128
    float* sqj  = sqi + 128;                 // 64
    float* sbd  = sqj + 64;                  // 128*20
    int*   sbi  = (int*)(sbd + 128*KNN);     // 128*20

    int tid = threadIdx.x, lane = tid & 31, warp = tid >> 5;
    int g4 = lane >> 2, tig = lane & 3;
    int wm = warp >> 1, wn = warp & 1;       // 4 m-warps x 2 n-warps; tile 32x32
    int b = blockIdx.y;
    int i0 = b*PP + blockIdx.x*128;
    const float4* x1v = (const float4*)g_x1;

    for (int fi = tid; fi < 128*16; fi += 256) {
        int pt = fi >> 4, q = fi & 15;
        float4 v = x1v[(size_t)(i0+pt)*16 + q];
        *(float4*)&sA[pt*KF_LDA + q*4] =
            make_float4(tfbits(v.x), tfbits(v.y), tfbits(v.z), tfbits(v.w));
    }
    if (tid < 128) {
        float s = 0.f;
#pragma unroll
        for (int q = 0; q < 16; q++) {
            float4 v = x1v[(size_t)(i0+tid)*16 + q];
            s += v.x*v.x + v.y*v.y + v.z*v.z + v.w*v.w;
        }
        sqi[tid] = s;
    }

    int spt = tid & 127, ssc = tid >> 7;     // selection: point, scanner half
    float bd[KNN]; int bi[KNN];
#pragma unroll
    for (int t = 0; t < KNN; t++) { bd[t] = 3.4e38f; bi[t] = 0; }
    float mysq = 0.f;

    for (int jt = 0; jt < 16; jt++) {
        int j0 = b*PP + jt*64;
        __syncthreads();
#pragma unroll
        for (int r = 0; r < 4; r++) {
            int fi = tid + r*256;
            int pt = fi >> 4, q = fi & 15;
            float4 v = x1v[(size_t)(j0+pt)*16 + q];
            *(float4*)&sB[pt*KF_LDA + q*4] =
                make_float4(tfbits(v.x), tfbits(v.y), tfbits(v.z), tfbits(v.w));
        }
        if (tid < 64) {
            float s = 0.f;
#pragma unroll
            for (int q = 0; q < 16; q++) {
                float4 v = x1v[(size_t)(j0+tid)*16 + q];
                s += v.x*v.x + v.y*v.y + v.z*v.z + v.w*v.w;
            }
            sqj[tid] = s;
        }
        __syncthreads();
        // GEMM dot[128 i][64 j], K=64; warp tile 32x32
        float acc[2][4][4];
#pragma unroll
        for (int mi = 0; mi < 2; mi++)
#pragma unroll
            for (int ni = 0; ni < 4; ni++)
#pragma unroll
                for (int c = 0; c < 4; c++) acc[mi][ni][c] = 0.f;
#pragma unroll
        for (int ks = 0; ks < 8; ks++) {
            int k0 = ks*8;
            uint32_t A[2][4];
#pragma unroll
            for (int mi = 0; mi < 2; mi++) {
                int row = wm*32 + mi*16 + g4;
                A[mi][0] = __float_as_uint(sA[row*KF_LDA + k0 + tig]);
                A[mi][1] = __float_as_uint(sA[(row+8)*KF_LDA + k0 + tig]);
                A[mi][2] = __float_as_uint(sA[row*KF_LDA + k0 + tig + 4]);
                A[mi][3] = __float_as_uint(sA[(row+8)*KF_LDA + k0 + tig + 4]);
            }
            uint32_t Bf[4][2];
#pragma unroll
            for (int ni = 0; ni < 4; ni++) {
                int col = wn*32 + ni*8 + g4;
                Bf[ni][0] = __float_as_uint(sB[col*KF_LDA + k0 + tig]);
                Bf[ni][1] = __float_as_uint(sB[col*KF_LDA + k0 + tig + 4]);
            }
#pragma unroll
            for (int mi = 0; mi < 2; mi++)
#pragma unroll
                for (int ni = 0; ni < 4; ni++)
                    mma8(acc[mi][ni][0], acc[mi][ni][1], acc[mi][ni][2], acc[mi][ni][3],
                         A[mi][0], A[mi][1], A[mi][2], A[mi][3], Bf[ni][0], Bf[ni][1]);
        }
#pragma unroll
        for (int mi = 0; mi < 2; mi++) {
#pragma unroll
            for (int ni = 0; ni < 4; ni++) {
                int row = wm*32 + mi*16 + g4, col = wn*32 + ni*8 + tig*2;
                *(float2*)&sdot[row*KF_LDA + col]     = make_float2(acc[mi][ni][0], acc[mi][ni][1]);
                *(float2*)&sdot[(row+8)*KF_LDA + col] = make_float2(acc[mi][ni][2], acc[mi][ni][3]);
            }
        }
        __syncthreads();
        // split selection (8-wide gate): scanner ssc covers j-cols [ssc*32, ssc*32+32)
        {
            if (jt == 0) mysq = sqi[spt];
            const float4* drow4 = (const float4*)(sdot + spt*KF_LDA) + ssc*8;
            const float4* sqj4  = (const float4*)sqj + ssc*8;
            int jbase = jt*64 + ssc*32;
#pragma unroll 2
            for (int j8 = 0; j8 < 4; j8++) {
                float4 dva = drow4[2*j8], dvb = drow4[2*j8+1];
                float4 sva = sqj4[2*j8],  svb = sqj4[2*j8+1];
                float d0 = mysq + sva.x - 2.0f*dva.x;
                float d1 = mysq + sva.y - 2.0f*dva.y;
                float d2 = mysq + sva.z - 2.0f*dva.z;
                float d3 = mysq + sva.w - 2.0f*dva.w;
                float d4 = mysq + svb.x - 2.0f*dvb.x;
                float d5 = mysq + svb.y - 2.0f*dvb.y;
                float d6 = mysq + svb.z - 2.0f*dvb.z;
                float d7 = mysq + svb.w - 2.0f*dvb.w;
                float mn = fminf(fminf(fminf(d0, d1), fminf(d2, d3)),
                                 fminf(fminf(d4, d5), fminf(d6, d7)));
                if (mn < bd[KNN-1]) {
                    int jb = jbase + 8*j8;
                    topk_insert(bd, bi, d0, jb + 0);
                    topk_insert(bd, bi, d1, jb + 1);
                    topk_insert(bd, bi, d2, jb + 2);
                    topk_insert(bd, bi, d3, jb + 3);
                    topk_insert(bd, bi, d4, jb + 4);
                    topk_insert(bd, bi, d5, jb + 5);
                    topk_insert(bd, bi, d6, jb + 6);
                    topk_insert(bd, bi, d7, jb + 7);
                }
            }
        }
    }
    __syncthreads();
    if (ssc == 1) {
#pragma unroll
        for (int t = 0; t < KNN; t++) { sbd[spt*KNN + t] = bd[t]; sbi[spt*KNN + t] = bi[t]; }
    }
    __syncthreads();
    if (ssc == 0) {
        for (int t = 0; t < KNN; t++) {
            float d = sbd[spt*KNN + t];
            if (!(d < bd[KNN-1])) break;
            topk_insert(bd, bi, d, sbi[spt*KNN + t]);
        }
        int gi = i0 + spt;
#pragma unroll
        for (int t = 0; t < KNN; t++) g_idx[(size_t)gi*KNN + t] = b*PP + bi[t];
    }
}

// ---------------- EdgeConv2 v6: persistent grid-stride + flat build + coop base + diff GEMM ----------------
#define C2_LDD 68
#define C2_LDW 136
#define C2_LDB 132
__global__ __launch_bounds__(256, 2) void conv2_kernel(
    const float* __restrict__ w, const float* __restrict__ bias)
{
    extern __shared__ float sm[];
    float* sWb   = sm;                        // 64*136
    float* sD    = sm + 64*C2_LDW;            // 160*68
    float* sXi   = sD + 160*C2_LDD;           // 8*68
    float* sBase = sXi + 8*68;                // 8*132
    float* sbias = sBase + 8*C2_LDB;          // 128
    int*   sJ    = (int*)(sbias + 128);       // 160
    int*   sP    = sJ + 160;                  // 160

    int tid = threadIdx.x, lane = tid & 31, warp = tid >> 5;
    int g4 = lane >> 2, tig = lane & 3;
    int wm = warp >> 2, wn = warp & 3;
    int mB = wm*80, nB = wn*32;

    for (int fi = tid; fi < 2048; fi += 256) {
        int kk = fi >> 5, nq = fi & 31;
        float4 v = ((const float4*)w)[(64+kk)*32 + nq];
        *(float4*)&sWb[kk*C2_LDW + nq*4] =
            make_float4(tfbits(v.x), tfbits(v.y), tfbits(v.z), tfbits(v.w));
    }
    if (tid < 128) sbias[tid] = bias[tid];

    const float4* x1v = (const float4*)g_x1;

    for (int g = blockIdx.x; g < 4096; g += gridDim.x) {
        int ibase = g * 8;
        __syncthreads();
        if (tid < 128) {
            int p = tid >> 4, q = tid & 15;
            *(float4*)&sXi[p*68 + q*4] = x1v[(size_t)(ibase+p)*16 + q];
        }
        if (tid < 160) {
            int p = tid / 20;
            sJ[tid] = g_idx[(size_t)(ibase+p)*KNN + (tid - p*20)];
            sP[tid] = p;
        }
        __syncthreads();
#pragma unroll
        for (int it = 0; it < 10; it++) {
            int fi = tid + it*256;
            int row = fi >> 4, q = fi & 15;
            int j = sJ[row], p = sP[row];
            float4 xj = x1v[(size_t)j*16 + q];
            float4 xi = *(const float4*)&sXi[p*68 + q*4];
            *(float4*)&sD[row*C2_LDD + q*4] =
                make_float4(tfbits(xj.x-xi.x), tfbits(xj.y-xi.y),
                            tfbits(xj.z-xi.z), tfbits(xj.w-xi.w));
        }
        {
            int p = lane >> 2, c4 = lane & 3;
            int colq = warp*4 + c4;
            const float* xir = &sXi[p*68];
            float4 acc4 = ((const float4*)sbias)[colq];
#pragma unroll 8
            for (int k = 0; k < 64; k++) {
                float xv = xir[k];
                float4 wv = ((const float4*)w)[k*32 + colq];
                acc4.x = fmaf(xv, wv.x, acc4.x); acc4.y = fmaf(xv, wv.y, acc4.y);
                acc4.z = fmaf(xv, wv.z, acc4.z); acc4.w = fmaf(xv, wv.w, acc4.w);
            }
            *(float4*)&sBase[p*C2_LDB + colq*4] = acc4;
        }
        __syncthreads();
        float acc[5][4][4];
#pragma unroll
        for (int mi = 0; mi < 5; mi++)
#pragma unroll
            for (int ni = 0; ni < 4; ni++)
#pragma unroll
                for (int c = 0; c < 4; c++) acc[mi][ni][c] = 0.f;
#pragma unroll 1
        for (int ks = 0; ks < 8; ks++) {
            int k0 = ks*8;
            uint32_t A[5][4];
#pragma unroll
            for (int mi = 0; mi < 5; mi++) {
                int row = mB + mi*16 + g4;
                A[mi][0] = __float_as_uint(sD[row*C2_LDD + k0 + tig]);
                A[mi][1] = __float_as_uint(sD[(row+8)*C2_LDD + k0 + tig]);
                A[mi][2] = __float_as_uint(sD[row*C2_LDD + k0 + tig + 4]);
                A[mi][3] = __float_as_uint(sD[(row+8)*C2_LDD + k0 + tig + 4]);
            }
            uint32_t Bf[4][2];
#pragma unroll
            for (int ni = 0; ni < 4; ni++) {
                int col = nB + ni*8 + g4;
                Bf[ni][0] = __float_as_uint(sWb[(k0+tig)*C2_LDW + col]);
                Bf[ni][1] = __float_as_uint(sWb[(k0+tig+4)*C2_LDW + col]);
            }
#pragma unroll
            for (int mi = 0; mi < 5; mi++)
#pragma unroll
                for (int ni = 0; ni < 4; ni++)
                    mma8(acc[mi][ni][0], acc[mi][ni][1], acc[mi][ni][2], acc[mi][ni][3],
                         A[mi][0], A[mi][1], A[mi][2], A[mi][3], Bf[ni][0], Bf[ni][1]);
        }
        float pm[4][4][2];
#pragma unroll
        for (int p = 0; p < 4; p++)
#pragma unroll
            for (int ni = 0; ni < 4; ni++) { pm[p][ni][0] = -3.4e38f; pm[p][ni][1] = -3.4e38f; }
        bool hi = (g4 >= 4);
#pragma unroll
        for (int ni = 0; ni < 4; ni++) {
            pm[0][ni][0] = fmaxf(pm[0][ni][0], acc[0][ni][0]);
            pm[0][ni][1] = fmaxf(pm[0][ni][1], acc[0][ni][1]);
            if (!hi) { pm[0][ni][0] = fmaxf(pm[0][ni][0], acc[1][ni][0]);
                       pm[0][ni][1] = fmaxf(pm[0][ni][1], acc[1][ni][1]); }
            else     { pm[1][ni][0] = fmaxf(pm[1][ni][0], acc[1][ni][0]);
                       pm[1][ni][1] = fmaxf(pm[1][ni][1], acc[1][ni][1]); }
            pm[1][ni][0] = fmaxf(pm[1][ni][0], acc[2][ni][0]);
            pm[1][ni][1] = fmaxf(pm[1][ni][1], acc[2][ni][1]);
            pm[2][ni][0] = fmaxf(pm[2][ni][0], acc[3][ni][0]);
            pm[2][ni][1] = fmaxf(pm[2][ni][1], acc[3][ni][1]);
            pm[3][ni][0] = fmaxf(pm[3][ni][0], acc[4][ni][0]);
            pm[3][ni][1] = fmaxf(pm[3][ni][1], acc[4][ni][1]);
            pm[0][ni][0] = fmaxf(pm[0][ni][0], acc[0][ni][2]);
            pm[0][ni][1] = fmaxf(pm[0][ni][1], acc[0][ni][3]);
            pm[1][ni][0] = fmaxf(pm[1][ni][0], acc[1][ni][2]);
            pm[1][ni][1] = fmaxf(pm[1][ni][1], acc[1][ni][3]);
            pm[2][ni][0] = fmaxf(pm[2][ni][0], acc[2][ni][2]);
            pm[2][ni][1] = fmaxf(pm[2][ni][1], acc[2][ni][3]);
            if (!hi) { pm[2][ni][0] = fmaxf(pm[2][ni][0], acc[3][ni][2]);
                       pm[2][ni][1] = fmaxf(pm[2][ni][1], acc[3][ni][3]); }
            else     { pm[3][ni][0] = fmaxf(pm[3][ni][0], acc[3][ni][2]);
                       pm[3][ni][1] = fmaxf(pm[3][ni][1], acc[3][ni][3]); }
            pm[3][ni][0] = fmaxf(pm[3][ni][0], acc[4][ni][2]);
            pm[3][ni][1] = fmaxf(pm[3][ni][1], acc[4][ni][3]);
        }
#pragma unroll
        for (int off = 4; off < 32; off <<= 1)
#pragma unroll
            for (int p = 0; p < 4; p++)
#pragma unroll
                for (int ni = 0; ni < 4; ni++) {
                    pm[p][ni][0] = fmaxf(pm[p][ni][0], __shfl_xor_sync(0xffffffff, pm[p][ni][0], off));
                    pm[p][ni][1] = fmaxf(pm[p][ni][1], __shfl_xor_sync(0xffffffff, pm[p][ni][1], off));
                }
        if (g4 == 0) {
#pragma unroll
            for (int p = 0; p < 4; p++) {
                int wp = wm*4 + p;
#pragma unroll
                for (int ni = 0; ni < 4; ni++) {
                    int col = nB + ni*8 + tig*2;
                    float b0v = sBase[wp*C2_LDB + col];
                    float b1v = sBase[wp*C2_LDB + col + 1];
                    float2 o;
                    o.x = fmaxf(pm[p][ni][0] + b0v, 0.f);
                    o.y = fmaxf(pm[p][ni][1] + b1v, 0.f);
                    *(float2*)&g_x2[(size_t)(ibase+wp)*128 + col] = o;
                }
            }
        }
    }
}

// ---------------- l1 (192->1024) tf32 GEMM, k-chunk 32, + fused relu + P-max ----------------
#define L1_LDA 36
__global__ __launch_bounds__(256) void l1max_kernel(
    const float* __restrict__ w, const float* __restrict__ bias)
{
    __shared__ float sA[128*L1_LDA];
    __shared__ float sB[32*136];
    __shared__ float sbias[128];
    __shared__ unsigned int sred[128];
    int tid = threadIdx.x;
    int lane = tid & 31, warp = tid >> 5;
    int g4 = lane >> 2, tig = lane & 3;
    int b = blockIdx.z;
    int n0 = blockIdx.x * 128, m0 = blockIdx.y * 128;
    int pbase = b * PP + m0;
    const float4* x1v = (const float4*)g_x1;
    const float4* x2v = (const float4*)g_x2;
    const float4* wv  = (const float4*)w;
    if (tid < 128) { sred[tid] = 0u; sbias[tid] = bias[n0 + tid]; }

    int wm = warp >> 2, wn = warp & 3;
    float acc[4][4][4];
#pragma unroll
    for (int mi = 0; mi < 4; mi++)
#pragma unroll
        for (int ni = 0; ni < 4; ni++)
#pragma unroll
            for (int c = 0; c < 4; c++) acc[mi][ni][c] = 0.f;

    for (int ks = 0; ks < 6; ks++) {
        __syncthreads();
#pragma unroll
        for (int r = 0; r < 4; r++) {
            int fi = tid + r*256;
            int pt = fi >> 3, kq = fi & 7;
            float4 v = (ks < 2) ? x1v[(size_t)(pbase+pt)*16 + ks*8 + kq]
                                : x2v[(size_t)(pbase+pt)*32 + (ks-2)*8 + kq];
            *(float4*)&sA[pt*L1_LDA + kq*4] =
                make_float4(tfbits(v.x), tfbits(v.y), tfbits(v.z), tfbits(v.w));
        }
#pragma unroll
        for (int r = 0; r < 4; r++) {
            int fi = tid + r*256;
            int kk = fi >> 5, nq = fi & 31;
            float4 v = wv[(size_t)(ks*32+kk)*256 + (n0>>2) + nq];
            *(float4*)&sB[kk*136 + nq*4] =
                make_float4(tfbits(v.x), tfbits(v.y), tfbits(v.z), tfbits(v.w));
        }
        __syncthreads();
#pragma unroll
        for (int kh = 0; kh < 4; kh++) {
            int k0 = kh*8;
            uint32_t A[4][4];
#pragma unroll
            for (int mi = 0; mi < 4; mi++) {
                int row = wm*64 + mi*16 + g4;
                A[mi][0] = __float_as_uint(sA[row*L1_LDA + k0 + tig]);
                A[mi][1] = __float_as_uint(sA[(row+8)*L1_LDA + k0 + tig]);
                A[mi][2] = __float_as_uint(sA[row*L1_LDA + k0 + tig + 4]);
                A[mi][3] = __float_as_uint(sA[(row+8)*L1_LDA + k0 + tig + 4]);
            }
            uint32_t Bf[4][2];
#pragma unroll
            for (int ni = 0; ni < 4; ni++) {
                int col = wn*32 + ni*8 + g4;
                Bf[ni][0] = __float_as_uint(sB[(k0+tig)*136 + col]);
                Bf[ni][1] = __float_as_uint(sB[(k0+tig+4)*136 + col]);
            }
#pragma unroll
            for (int mi = 0; mi < 4; mi++)
#pragma unroll
                for (int ni = 0; ni < 4; ni++)
                    mma8(acc[mi][ni][0], acc[mi][ni][1], acc[mi][ni][2], acc[mi][ni][3],
                         A[mi][0], A[mi][1], A[mi][2], A[mi][3], Bf[ni][0], Bf[ni][1]);
        }
    }
#pragma unroll
    for (int ni = 0; ni < 4; ni++) {
        float v0 = -3.4e38f, v1 = -3.4e38f;
#pragma unroll
        for (int mi = 0; mi < 4; mi++) {
            v0 = fmaxf(v0, fmaxf(acc[mi][ni][0], acc[mi][ni][2]));
            v1 = fmaxf(v1, fmaxf(acc[mi][ni][1], acc[mi][ni][3]));
        }
#pragma unroll
        for (int off = 4; off < 32; off <<= 1) {
            v0 = fmaxf(v0, __shfl_xor_sync(0xffffffff, v0, off));
            v1 = fmaxf(v1, __shfl_xor_sync(0xffffffff, v1, off));
        }
        if (g4 == 0) {
            int col = wn*32 + ni*8 + tig*2;
            float a0 = fmaxf(v0 + sbias[col], 0.f);
            float a1 = fmaxf(v1 + sbias[col+1], 0.f);
            atomicMax(&sred[col],   __float_as_uint(a0));
            atomicMax(&sred[col+1], __float_as_uint(a1));
        }
    }
    __syncthreads();
    if (tid < 128) atomicMax(&g_pool[b*1024 + n0 + tid], sred[tid]);
}

// ---------------- head0: h0 = relu(pool @ m_w0 + b0), grid (2, 32) ----------------
__global__ __launch_bounds__(256) void head0_kernel(
    const float* __restrict__ w0, const float* __restrict__ b0)
{
    __shared__ float sp[1024];
    int b = blockIdx.y, tid = threadIdx.x;
    int o = blockIdx.x * 256 + tid;
    for (int c = tid; c < 1024; c += 256) sp[c] = __uint_as_float(g_pool[b*1024 + c]);
    __syncthreads();
    float a0 = 0.f, a1 = 0.f, a2 = 0.f, a3 = 0.f;
    for (int c = 0; c < 1024; c += 4) {
        a0 = fmaf(sp[c+0], w0[(size_t)(c+0)*512 + o], a0);
        a1 = fmaf(sp[c+1], w0[(size_t)(c+1)*512 + o], a1);
        a2 = fmaf(sp[c+2], w0[(size_t)(c+2)*512 + o], a2);
        a3 = fmaf(sp[c+3], w0[(size_t)(c+3)*512 + o], a3);
    }
    g_h0[b*512 + o] = fmaxf(((a0 + a1) + (a2 + a3)) + b0[o], 0.f);
}

// ---------------- head1: 512->256 relu ->40 + log_softmax, grid 32 ----------------
__global__ __launch_bounds__(256) void head1_kernel(
    const float* __restrict__ w1, const float* __restrict__ b1,
    const float* __restrict__ w2, const float* __restrict__ b2,
    float* __restrict__ out)
{
    __shared__ float sh0[512], sh1[256], sl[40], red[2];
    int b = blockIdx.x, tid = threadIdx.x;
    for (int c = tid; c < 512; c += 256) sh0[c] = g_h0[b*512 + c];
    __syncthreads();
    {
        float a0 = 0.f, a1 = 0.f;
        for (int c = 0; c < 512; c += 2) {
            a0 = fmaf(sh0[c],   w1[(size_t)c*256 + tid],     a0);
            a1 = fmaf(sh0[c+1], w1[(size_t)(c+1)*256 + tid], a1);
        }
        sh1[tid] = fmaxf(a0 + a1 + b1[tid], 0.f);
    }
    __syncthreads();
    if (tid < 40) {
        float a = b2[tid];
        for (int c = 0; c < 256; c++) a += sh1[c] * w2[c*40 + tid];
        sl[tid] = a;
    }
    __syncthreads();
    if (tid == 0) {
        float mxv = -3.4e38f;
        for (int t = 0; t < 40; t++) mxv = fmaxf(mxv, sl[t]);
        float s = 0.f;
        for (int t = 0; t < 40; t++) s += expf(sl[t] - mxv);
        red[0] = mxv; red[1] = logf(s);
    }
    __syncthreads();
    if (tid < 40) out[b*40 + tid] = sl[tid] - red[0] - red[1];
}

// ---------------- launch ----------------
extern "C" void kernel_launch(void* const* d_in, const int* in_sizes, int n_in,
                              void* d_out, int out_size)
{
    const float* pos   = (const float*)d_in[0];
    const float* c1_w0 = (const float*)d_in[2];
    const float* c1_b0 = (const float*)d_in[3];
    const float* c1_w1 = (const float*)d_in[4];
    const float* c1_b1 = (const float*)d_in[5];
    const float* c1_w2 = (const float*)d_in[6];
    const float* c1_b2 = (const float*)d_in[7];
    const float* c2_w0 = (const float*)d_in[8];
    const float* c2_b0 = (const float*)d_in[9];
    const float* l1_w  = (const float*)d_in[10];
    const float* l1_b  = (const float*)d_in[11];
    const float* m_w0  = (const float*)d_in[12];
    const float* m_b0  = (const float*)d_in[13];
    const float* m_w1  = (const float*)d_in[14];
    const float* m_b1  = (const float*)d_in[15];
    const float* m_w2  = (const float*)d_in[16];
    const float* m_b2  = (const float*)d_in[17];
    float* out = (float*)d_out;

    const int smem_kpos  = 4096*4 + 5120*4 + 5120*4;                                     // 57344
    const int smem_conv1 = (576 + 4608 + 128 + 160*C1_LDD) * 4;                          // 64768
    const int smem_knn2  = (128*KF_LDA + 64*KF_LDA + 128*KF_LDA + 128 + 64
                            + 128*KNN + 128*KNN) * 4;                                     // 108288
    const int smem_conv2 = (64*C2_LDW + 160*C2_LDD + 8*68 + 8*C2_LDB + 128 + 320) * 4;   // ~86.5 KB

    cudaFuncSetAttribute(knn_pos_kernel,  cudaFuncAttributeMaxDynamicSharedMemorySize, smem_kpos);
    cudaFuncSetAttribute(conv1_kernel,    cudaFuncAttributeMaxDynamicSharedMemorySize, smem_conv1);
    cudaFuncSetAttribute(knn_feat_kernel, cudaFuncAttributeMaxDynamicSharedMemorySize, smem_knn2);
    cudaFuncSetAttribute(conv2_kernel,    cudaFuncAttributeMaxDynamicSharedMemorySize, smem_conv2);

    fuse_w01_kernel<<<1, 512>>>(c1_w0, c1_b0, c1_w1, c1_b1);
    knn_pos_kernel<<<dim3(4, 32), 512, smem_kpos>>>(pos);
    conv1_kernel<<<296, 256, smem_conv1>>>(pos, c1_w2, c1_b2);
    knn_feat_kernel<<<dim3(8, 32), 256, smem_knn2>>>();
    conv2_kernel<<<296, 256, smem_conv2>>>(c2_w0, c2_b0);
    l1max_kernel<<<dim3(8, 8, 32), 256>>>(l1_w, l1_b);
    head0_kernel<<<dim3(2, 32), 256>>>(m_w0, m_b0);
    head1_kernel<<<32, 256>>>(m_w1, m_b1, m_w2, m_b2, out);
}